// round 12
// baseline (speedup 1.0000x reference)
#include <cuda_runtime.h>
#include <math.h>

#define NN   128
#define NE   512
#define HID  64
#define BB   64
#define NP   16384     // NN*NN
#define SMEAR (-0.39f)
#define FEPS  1e-6f

// ---------------- device scratch (no allocation allowed) ----------------
__device__ float  g_n[2][2][NN][HID];     // [pingpong][mol][node][feat]
__device__ float  g_e[2][2][NE][HID];     // [pingpong][mol][edge][feat]
__device__ int    g_h[2][NN];
__device__ int    g_cnt[2][NN];
__device__ short  g_elist[2][NN][NE];
__device__ float  g_ap[2][NN][5];         // a_d, pol, K, dq, a_e
__device__ float  g_u[2][NN][HID];        // feats @ ppW0[0:64]
__device__ float  g_v[2][NN][HID];        // feats @ ppW0[64:128]
__device__ float  g_pp[11][NP];           // C6,C8,C10,r3,r4,r5,Act,bct,bd,be,Kp
__device__ float4 g_cpack[2][BB][NN];     // (cx,cy,cz,q)
__device__ float  g_qe[2][BB][NN];

// mila(x) = x * tanh(softplus(x-1)) = x * (1 - 2/((1+e^{x-1})^2 + 1))  (exact)
__device__ __forceinline__ float milaf(float x) {
    float t = expf(x - 1.0f);
    float a = 1.0f + t;
    float d = fmaf(a, a, 1.0f);
    return x * (1.0f - __fdividef(2.0f, d));
}
__device__ __forceinline__ float sspf(float x) {
    return fmaxf(x, 0.0f) + log1pf(expf(-fabsf(x))) + 0.001f;
}
__device__ __forceinline__ float wred(float v) {
    #pragma unroll
    for (int o = 16; o; o >>= 1) v += __shfl_xor_sync(0xffffffffu, v, o);
    return v;
}

// ---------------- GNN: embed + CSR build fused ----------------
__global__ void __launch_bounds__(256) k_embed(
                        const float* __restrict__ nodes1, const float* __restrict__ nodes2,
                        const float* __restrict__ edges1, const float* __restrict__ edges2,
                        const float* __restrict__ Wn, const float* __restrict__ bn,
                        const float* __restrict__ We, const float* __restrict__ be_,
                        const int* __restrict__ rcv1, const int* __restrict__ rcv2) {
    if (blockIdx.x == 321) {           // CSR build section
        int t = threadIdx.x;           // 256 threads
        int m = t >> 7, node = t & 127;
        const int* rcv = m ? rcv2 : rcv1;
        int c = 0;
        for (int e = 0; e < NE; e++) {
            if (rcv[e] == node) g_elist[m][node][c++] = (short)e;
        }
        g_cnt[m][node] = c;
        return;
    }
    int g = blockIdx.x * 256 + threadIdx.x;   // 82176 total
    if (g < 2 * NN * HID) {
        int m = g / (NN * HID);
        int r = g % (NN * HID);
        int i = r / HID, o = r % HID;
        const float* nd = m ? nodes2 : nodes1;
        float acc = bn[o];
        #pragma unroll
        for (int k = 0; k < 16; k++) acc = fmaf(nd[i * 16 + k], __ldg(Wn + k * HID + o), acc);
        g_n[0][m][i][o] = milaf(acc);
    } else if (g < 2 * NN * HID + 2 * NE * HID) {
        int r = g - 2 * NN * HID;
        int m = r / (NE * HID);
        r %= NE * HID;
        int ei = r / HID, o = r % HID;
        const float* ed = m ? edges2 : edges1;
        float acc = be_[o];
        #pragma unroll
        for (int k = 0; k < 8; k++) acc = fmaf(ed[ei * 8 + k], __ldg(We + k * HID + o), acc);
        g_e[0][m][ei][o] = milaf(acc);
    } else {
        int r = g - (2 * NN * HID + 2 * NE * HID);   // < 256
        int m = r >> 7, i = r & 127;
        const float* nd = m ? nodes2 : nodes1;
        float v0 = nd[i * 16];
        float mx = -1e30f;
        #pragma unroll
        for (int k = 1; k < 16; k++) mx = fmaxf(mx, nd[i * 16 + k]);
        g_h[m][i] = (v0 >= mx) ? 1 : 0;
    }
}

// ---------------- edge update: 256 blocks, 1 item/thread, 3 acc chains ----------------
__global__ void __launch_bounds__(256) k_edge(int s, int ib, int ob,
                       const int* __restrict__ snd1, const int* __restrict__ rcv1,
                       const int* __restrict__ snd2, const int* __restrict__ rcv2,
                       const float* __restrict__ Wge, const float* __restrict__ bge) {
    __shared__ float sW[192 * 64];           // 48KB: Wge[s] natural layout [k*64+o]
    const float* W = Wge + s * 192 * 64;
    #pragma unroll
    for (int k = 0; k < 48; k++) sW[threadIdx.x + 256 * k] = W[threadIdx.x + 256 * k];
    __syncthreads();
    int g = blockIdx.x * 256 + threadIdx.x;  // 65536 total, grid 256
    int m = g >> 15;
    int r = g & 32767;
    int e = r >> 6, o = r & 63;
    const int* snd = m ? snd2 : snd1;
    const int* rcv = m ? rcv2 : rcv1;
    int sidx = snd[e], ridx = rcv[e];
    const float4* er = (const float4*)&g_e[ib][m][e][0];
    const float4* nr = (const float4*)&g_n[ib][m][ridx][0];
    const float4* ns = (const float4*)&g_n[ib][m][sidx][0];
    float acc1 = bge[s * 64 + o];            // 3 independent chains for ILP
    float acc2 = 0.0f;
    float acc3 = 0.0f;
    #pragma unroll 4
    for (int c = 0; c < 16; c++) {
        float4 ev = er[c], rv = nr[c], sv = ns[c];
        int k4 = 4 * c;
        acc1 = fmaf(ev.x, sW[(k4 + 0) * 64 + o], acc1);
        acc2 = fmaf(rv.x, sW[(64 + k4 + 0) * 64 + o], acc2);
        acc3 = fmaf(sv.x, sW[(128 + k4 + 0) * 64 + o], acc3);
        acc1 = fmaf(ev.y, sW[(k4 + 1) * 64 + o], acc1);
        acc2 = fmaf(rv.y, sW[(64 + k4 + 1) * 64 + o], acc2);
        acc3 = fmaf(sv.y, sW[(128 + k4 + 1) * 64 + o], acc3);
        acc1 = fmaf(ev.z, sW[(k4 + 2) * 64 + o], acc1);
        acc2 = fmaf(rv.z, sW[(64 + k4 + 2) * 64 + o], acc2);
        acc3 = fmaf(sv.z, sW[(128 + k4 + 2) * 64 + o], acc3);
        acc1 = fmaf(ev.w, sW[(k4 + 3) * 64 + o], acc1);
        acc2 = fmaf(rv.w, sW[(64 + k4 + 3) * 64 + o], acc2);
        acc3 = fmaf(sv.w, sW[(128 + k4 + 3) * 64 + o], acc3);
    }
    g_e[ob][m][e][o] = milaf(acc1 + acc2 + acc3);
}

// ---------------- node update: 128 blocks x 128 threads, gmem weights, fused gather+post ----------------
__global__ void __launch_bounds__(128) k_node(int s, int ib, int ob, int last,
                       const float* __restrict__ Wgn, const float* __restrict__ bgn,
                       const float* __restrict__ apW0, const float* __restrict__ apb0,
                       const float* __restrict__ apW1, const float* __restrict__ apb1,
                       const float* __restrict__ apW2, const float* __restrict__ apb2,
                       const float* __restrict__ ppW0) {
    __shared__ float sagg[2][64];
    __shared__ float sf[128], sh1[128], sh2[128];
    int tid = threadIdx.x;
    int g = blockIdx.x * 128 + tid;           // 16384 total, grid 128
    int m = g >> 13;
    int i = (g >> 6) & 127;
    int o = g & 63;
    int nl = tid >> 6;                        // node slot within block (0..1)
    // fused segment-sum: gather this node's aggregated edge vector component o
    int cnt = g_cnt[m][i];
    float agg = 0.0f;
    for (int c = 0; c < cnt; c++) agg += g_e[ob][m][g_elist[m][i][c]][o];
    sagg[nl][o] = agg;
    __syncthreads();
    const float* W = Wgn + s * 128 * 64;
    const float4* nr = (const float4*)&g_n[ib][m][i][0];
    const float4* ar = (const float4*)&sagg[nl][0];
    float acc1 = bgn[s * 64 + o];
    float acc2 = 0.0f;
    #pragma unroll 8
    for (int c = 0; c < 16; c++) {
        float4 nv = nr[c], av = ar[c];
        int k4 = 4 * c;
        acc1 = fmaf(nv.x, __ldg(W + (k4 + 0) * 64 + o), acc1);
        acc2 = fmaf(av.x, __ldg(W + (64 + k4 + 0) * 64 + o), acc2);
        acc1 = fmaf(nv.y, __ldg(W + (k4 + 1) * 64 + o), acc1);
        acc2 = fmaf(av.y, __ldg(W + (64 + k4 + 1) * 64 + o), acc2);
        acc1 = fmaf(nv.z, __ldg(W + (k4 + 2) * 64 + o), acc1);
        acc2 = fmaf(av.z, __ldg(W + (64 + k4 + 2) * 64 + o), acc2);
        acc1 = fmaf(nv.w, __ldg(W + (k4 + 3) * 64 + o), acc1);
        acc2 = fmaf(av.w, __ldg(W + (64 + k4 + 3) * 64 + o), acc2);
    }
    float val = milaf(acc1 + acc2);
    g_n[ob][m][i][o] = val;
    if (last) {   // fused per-node post: atom-props MLP + pair-layer-0 factorization
        sf[tid] = val;
        __syncthreads();
        const float* f = &sf[nl * 64];
        float a = apb0[o], su = 0.0f, sv = 0.0f;
        #pragma unroll 8
        for (int k = 0; k < 64; k++) {
            float fk = f[k];
            a  = fmaf(fk, __ldg(apW0 + k * 64 + o), a);
            su = fmaf(fk, __ldg(ppW0 + k * 64 + o), su);
            sv = fmaf(fk, __ldg(ppW0 + (64 + k) * 64 + o), sv);
        }
        sh1[tid] = milaf(a);
        g_u[m][i][o] = su;
        g_v[m][i][o] = sv;
        __syncthreads();
        float a1 = apb1[o];
        const float* h1 = &sh1[nl * 64];
        #pragma unroll 8
        for (int k = 0; k < 64; k++) a1 = fmaf(h1[k], __ldg(apW1 + k * 64 + o), a1);
        sh2[tid] = milaf(a1);
        __syncthreads();
        if (o < 5) {
            float a2 = apb2[o];
            const float* h2 = &sh2[nl * 64];
            for (int k = 0; k < 64; k++) a2 = fmaf(h2[k], __ldg(apW2 + k * 5 + o), a2);
            g_ap[m][i][o] = sspf(a2);
        }
    }
}

// ---------------- pair MLP (warp per pair) + fold-in of per-(b,node) prep ----------------
__global__ void __launch_bounds__(256) k_pair(
                       const float* __restrict__ ppb0, const float* __restrict__ ppW1,
                       const float* __restrict__ ppb1, const float* __restrict__ ppW2,
                       const float* __restrict__ ppb2, const float* __restrict__ mp,
                       const float* __restrict__ coords1, const float* __restrict__ coords2) {
    __shared__ float sW1[4096];
    __shared__ float sW2[320];
    __shared__ float sb0[64], sb1[64], sb2[8];
    __shared__ float sh[8][64];
    int tid = threadIdx.x;
    int gq = blockIdx.x * 256 + tid;
    if (gq < 2 * BB * NN) {
        int m = gq >> 13;
        int r = gq & 8191;
        int b = r >> 7, n = r & 127;
        float q = mp[(m * BB + b) * NN + n];
        float dq = g_ap[m][n][3];
        float qe = g_h[m][n] ? (1.0f - q) : (2.0f + dq - q);
        g_qe[m][b][n] = qe;
        const float* cc = (m ? coords2 : coords1) + (b * NN + n) * 3;
        g_cpack[m][b][n] = make_float4(cc[0], cc[1], cc[2], q);
    }
    for (int k = tid; k < 4096; k += 256) sW1[k] = ppW1[k];
    for (int k = tid; k < 320; k += 256) sW2[k] = ppW2[k];
    if (tid < 64) { sb0[tid] = ppb0[tid]; sb1[tid] = ppb1[tid]; }
    if (tid < 5)  sb2[tid] = ppb2[tid];
    __syncthreads();
    int warp = tid >> 5, lane = tid & 31;
    float* hw = sh[warp];
    for (int t = 0; t < 8; t++) {
        int p = blockIdx.x * 64 + warp * 8 + t;
        int i = p >> 7, j = p & 127;
        float pr0 = 0, pr1 = 0, pr2 = 0, pr3 = 0, pr4 = 0;
        #pragma unroll
        for (int d = 0; d < 2; d++) {
            const float* U = d ? g_u[1][j] : g_u[0][i];
            const float* V = d ? g_v[0][i] : g_v[1][j];
            float2 uu = *(const float2*)(U + 2 * lane);
            float2 vv = *(const float2*)(V + 2 * lane);
            float h0 = milaf(uu.x + vv.x + sb0[2 * lane]);
            float h1 = milaf(uu.y + vv.y + sb0[2 * lane + 1]);
            __syncwarp();
            hw[2 * lane] = h0; hw[2 * lane + 1] = h1;
            __syncwarp();
            float a0 = sb1[2 * lane], a1 = sb1[2 * lane + 1];
            #pragma unroll 8
            for (int k = 0; k < 64; k++) {
                float hk = hw[k];
                float2 w = *(const float2*)(sW1 + k * 64 + 2 * lane);
                a0 = fmaf(hk, w.x, a0);
                a1 = fmaf(hk, w.y, a1);
            }
            float g0 = milaf(a0), g1 = milaf(a1);
            const float* w2a = sW2 + (2 * lane) * 5;
            const float* w2b = sW2 + (2 * lane + 1) * 5;
            float p0 = g0 * w2a[0] + g1 * w2b[0];
            float p1 = g0 * w2a[1] + g1 * w2b[1];
            float p2 = g0 * w2a[2] + g1 * w2b[2];
            float p3 = g0 * w2a[3] + g1 * w2b[3];
            float p4 = g0 * w2a[4] + g1 * w2b[4];
            p0 = wred(p0); p1 = wred(p1); p2 = wred(p2); p3 = wred(p3); p4 = wred(p4);
            pr0 += sspf(p0 + sb2[0]);
            pr1 += sspf(p1 + sb2[1]);
            pr2 += sspf(p2 + sb2[2]);
            pr3 += sspf(p3 + sb2[3]);
            pr4 += sspf(p4 + sb2[4]);
        }
        if (lane == 0) {
            float C6 = pr0, C8 = pr1, C10 = pr2, Act = pr3, bct = pr4;
            float r02 = C8 / (C6 + FEPS);
            float r3 = r02 * r02 * r02, r4 = r3 * r02, r5 = r4 * r02;
            float bd = sqrtf(g_ap[0][i][0] * g_ap[1][j][0]);
            float be = sqrtf(g_ap[0][i][4] * g_ap[1][j][4]);
            float Kp = g_ap[0][i][2] * g_ap[1][j][2];
            g_pp[0][p] = C6;  g_pp[1][p] = C8;  g_pp[2][p] = C10;
            g_pp[3][p] = r3;  g_pp[4][p] = r4;  g_pp[5][p] = r5;
            g_pp[6][p] = Act; g_pp[7][p] = bct; g_pp[8][p] = bd;
            g_pp[9][p] = be;  g_pp[10][p] = Kp;
        }
    }
}

// ---------------- mega-fused induction + energy: one block per batch b ----------------
#define IND_SMEM_FLOATS (33024 + 6*128*4 + 256 + 4*256*4)

__global__ void __launch_bounds__(1024, 1) k_induct(const float* __restrict__ dist,
                                                    float* __restrict__ out) {
    extern __shared__ float smem[];
    float*  c3s = smem;
    float*  c5s = smem + 16512;
    float4* cpA = (float4*)(smem + 33024);
    float4* cpB = cpA + 128;
    float4* muA = cpB + 128;
    float4* muB = muA + 128;
    float4* e0A = muB + 128;
    float4* e0B = e0A + 128;
    float*  qeS = (float*)(e0B + 128);
    float4* part = (float4*)(qeS + 256);
    float*  ired = c3s;                       // safe reuse after iterations

    int b = blockIdx.x;
    int tid = threadIdx.x;                    // 1024 threads

    // ---- stage per-atom data ----
    if (tid < 256) {
        int m = tid >> 7, n = tid & 127;
        float4 cp = g_cpack[m][b][n];
        (m ? cpB : cpA)[n] = cp;
        qeS[tid] = g_qe[m][b][n];
        float pol = g_ap[m][n][1];
        (m ? e0B : e0A)[n] = make_float4(0.0f, 0.0f, 0.0f, pol);
    }
    __syncthreads();

    // ---- compute c3/c5 coefficients (16 pairs per thread, coalesced) ----
    #pragma unroll
    for (int k = 0; k < 16; k++) {
        int p = tid + 1024 * k;
        int i = p >> 7, j = p & 127;
        float R = dist[b * NP + p];
        float au = sqrtf(e0A[i].w * e0B[j].w) + FEPS;
        float R2 = R * R;
        float r3raw = R2 * R;
        float u3 = __fdividef(r3raw, au);
        float exu = expf(SMEAR * u3);
        float lam3 = 1.0f - exu;
        float lam5 = 1.0f - (1.0f - SMEAR * u3) * exu;
        c3s[i * 129 + j] = __fdividef(lam3, r3raw + FEPS);
        c5s[i * 129 + j] = __fdividef(3.0f * lam5, R2 * r3raw + FEPS);
    }
    __syncthreads();

    // ---- warp mapping: 8 row-groups x 4 col-slices ----
    int w = tid >> 5, lane = tid & 31;
    int gg = w & 7;                           // row group (32 rows)
    int slice = w >> 3;                       // col slice (32 cols)
    int rrow = gg * 32 + lane;                // 0..255
    int mol = rrow >> 7;
    int n = rrow & 127;
    float4 cs = mol ? cpB[n] : cpA[n];
    const float4* cop = mol ? cpA : cpB;
    int c0 = slice * 32;

    // ---- E0 pass:  E0_row = cs*Σ(q c3) − Σ(q c3 co) ----
    {
        float sk = 0, sx = 0, sy = 0, sz = 0;
        #pragma unroll 4
        for (int c = 0; c < 32; c++) {
            int oth = c0 + c;
            float c3 = mol ? c3s[oth * 129 + n] : c3s[n * 129 + oth];
            float4 co = cop[oth];
            float wq = co.w * c3;
            sk += wq;
            sx = fmaf(wq, co.x, sx);
            sy = fmaf(wq, co.y, sy);
            sz = fmaf(wq, co.z, sz);
        }
        part[slice * 256 + rrow] = make_float4(fmaf(cs.x, sk, -sx),
                                               fmaf(cs.y, sk, -sy),
                                               fmaf(cs.z, sk, -sz), 0.0f);
    }
    __syncthreads();
    if (tid < 256) {
        float4 a0 = part[tid], a1 = part[256 + tid], a2 = part[512 + tid], a3 = part[768 + tid];
        float ex0 = a0.x + a1.x + a2.x + a3.x;
        float ey0 = a0.y + a1.y + a2.y + a3.y;
        float ez0 = a0.z + a1.z + a2.z + a3.z;
        int m = tid >> 7, nn = tid & 127;
        float4* e0p = m ? e0B : e0A;
        float pol = e0p[nn].w;
        e0p[nn] = make_float4(ex0, ey0, ez0, pol);
        float mux = pol * ex0, muy = pol * ey0, muz = pol * ez0;
        float4 cc = m ? cpB[nn] : cpA[nn];
        float dcm = cc.x * mux + cc.y * muy + cc.z * muz;
        (m ? muB : muA)[nn] = make_float4(mux, muy, muz, dcm);
    }
    __syncthreads();

    // ---- 8 fixed-point iterations, mu resident in smem ----
    const float4* mop = mol ? muA : muB;
    for (int it = 0; it < 8; it++) {
        float sk = 0, sx = 0, sy = 0, sz = 0, tx = 0, ty = 0, tz = 0;
        #pragma unroll 4
        for (int c = 0; c < 32; c++) {
            int oth = c0 + c;
            float c3, c5;
            if (mol) { c3 = c3s[oth * 129 + n]; c5 = c5s[oth * 129 + n]; }
            else     { c3 = c3s[n * 129 + oth]; c5 = c5s[n * 129 + oth]; }
            float4 mo = mop[oth];
            float4 co = cop[oth];
            float rm = fmaf(cs.x, mo.x, fmaf(cs.y, mo.y, fmaf(cs.z, mo.z, -mo.w)));
            float k5 = c5 * rm;
            sk += k5;
            sx = fmaf(k5, co.x, sx);
            sy = fmaf(k5, co.y, sy);
            sz = fmaf(k5, co.z, sz);
            tx = fmaf(c3, mo.x, tx);
            ty = fmaf(c3, mo.y, ty);
            tz = fmaf(c3, mo.z, tz);
        }
        part[slice * 256 + rrow] = make_float4(fmaf(cs.x, sk, -sx) - tx,
                                               fmaf(cs.y, sk, -sy) - ty,
                                               fmaf(cs.z, sk, -sz) - tz, 0.0f);
        __syncthreads();
        if (tid < 256) {
            float4 a0 = part[tid], a1 = part[256 + tid], a2 = part[512 + tid], a3 = part[768 + tid];
            float ax = a0.x + a1.x + a2.x + a3.x;
            float ay = a0.y + a1.y + a2.y + a3.y;
            float az = a0.z + a1.z + a2.z + a3.z;
            int m = tid >> 7, nn = tid & 127;
            float4 e0 = (m ? e0B : e0A)[nn];
            float4 mo = (m ? muB : muA)[nn];
            float pol = e0.w;
            float fx = e0.x + ax, fy = e0.y + ay, fz = e0.z + az;
            float mux = fmaf(0.75f * pol, fx, 0.25f * mo.x);
            float muy = fmaf(0.75f * pol, fy, 0.25f * mo.y);
            float muz = fmaf(0.75f * pol, fz, 0.25f * mo.z);
            float4 cc = m ? cpB[nn] : cpA[nn];
            float dcm = cc.x * mux + cc.y * muy + cc.z * muz;
            (m ? muB : muA)[nn] = make_float4(mux, muy, muz, dcm);
        }
        __syncthreads();
    }

    // ---- energy terms (16 pairs per thread, coalesced) ----
    float es_a = 0, ex_a = 0, dsp_a = 0, ct_a = 0;
    #pragma unroll 4
    for (int k = 0; k < 16; k++) {
        int p = tid + 1024 * k;
        int i = p >> 7, j = p & 127;
        float R = dist[b * NP + p];
        float C6  = g_pp[0][p], C8  = g_pp[1][p], C10 = g_pp[2][p];
        float r3  = g_pp[3][p], r4  = g_pp[4][p], r5  = g_pp[5][p];
        float Act = g_pp[6][p], bct = g_pp[7][p];
        float bd  = g_pp[8][p], be  = g_pp[9][p], Kp = g_pp[10][p];
        float4 c1p = cpA[i];
        float4 c2p = cpB[j];
        float4 m1 = muA[i];
        float4 m2 = muB[j];
        float B0 = __fdividef(1.0f, R + FEPS);
        float ebd = expf(-bd * R);
        es_a += c1p.w * c2p.w * (1.0f - fmaf(0.5f * bd, R, 1.0f) * ebd) * B0;
        ct_a += Act * expf(-bct * R);
        float R2 = R * R;
        if (R2 < 2500.0f) {
            float R6 = R2 * R2 * R2;
            float R8 = R6 * R2;
            float R10 = R8 * R2;
            dsp_a -= __fdividef(C6, R6 + r3) + __fdividef(C8, R8 + r4) + __fdividef(C10, R10 + r5);
        }
        float rhx = (c2p.x - c1p.x) * B0;
        float rhy = (c2p.y - c1p.y) * B0;
        float rhz = (c2p.z - c1p.z) * B0;
        float proj = (m1.x - m2.x) * rhx + (m1.y - m2.y) * rhy + (m1.z - m2.z) * rhz;
        ex_a += Kp * qeS[i] * qeS[128 + j] * (1.0f + proj) * expf(-be * R) * B0;
    }
    float iev = 0.0f;
    if (tid < 256) {
        int m = tid >> 7, nn = tid & 127;
        float4 mo = (m ? muB : muA)[nn];
        float4 e0 = (m ? e0B : e0A)[nn];
        iev = mo.x * e0.x + mo.y * e0.y + mo.z * e0.z;
    }
    __syncthreads();                          // all c3s/part reads complete
    part[tid] = make_float4(es_a, ex_a, dsp_a, ct_a);
    ired[tid] = iev;
    __syncthreads();
    for (int s = 512; s; s >>= 1) {
        if (tid < s) {
            float4 a = part[tid], c = part[tid + s];
            part[tid] = make_float4(a.x + c.x, a.y + c.y, a.z + c.z, a.w + c.w);
            ired[tid] += ired[tid + s];
        }
        __syncthreads();
    }
    if (tid == 0) {
        float4 a = part[0];
        float in_t = -0.5f * ired[0] - a.w;
        out[b]        = a.y + a.z + a.x + in_t;
        out[64 + b]   = a.x;
        out[128 + b]  = in_t;
        out[192 + b]  = a.y;
        out[256 + b]  = a.z;
    }
}

// ---------------- launch ----------------
extern "C" void kernel_launch(void* const* d_in, const int* in_sizes, int n_in,
                              void* d_out, int out_size) {
    const float* nodes1    = (const float*)d_in[0];
    const float* edges1    = (const float*)d_in[1];
    const int*   senders1  = (const int*)d_in[2];
    const int*   receivers1= (const int*)d_in[3];
    const float* nodes2    = (const float*)d_in[4];
    const float* edges2    = (const float*)d_in[5];
    const int*   senders2  = (const int*)d_in[6];
    const int*   receivers2= (const int*)d_in[7];
    const float* coords1   = (const float*)d_in[8];
    const float* coords2   = (const float*)d_in[9];
    const float* dist;
    const float* mp;
    if (in_sizes[10] == 2 * BB * NN) {        // multipoles came first
        mp   = (const float*)d_in[10];
        dist = (const float*)d_in[11];
    } else {                                  // distance_matrices first (setup order)
        dist = (const float*)d_in[10];
        mp   = (const float*)d_in[11];
    }
    const float* W_emb_node = (const float*)d_in[12];
    const float* b_emb_node = (const float*)d_in[13];
    const float* W_emb_edge = (const float*)d_in[14];
    const float* b_emb_edge = (const float*)d_in[15];
    const float* W_gn_edge  = (const float*)d_in[16];
    const float* b_gn_edge  = (const float*)d_in[17];
    const float* W_gn_node  = (const float*)d_in[18];
    const float* b_gn_node  = (const float*)d_in[19];
    const float* pp_W0 = (const float*)d_in[20];
    const float* pp_b0 = (const float*)d_in[21];
    const float* pp_W1 = (const float*)d_in[22];
    const float* pp_b1 = (const float*)d_in[23];
    const float* pp_W2 = (const float*)d_in[24];
    const float* pp_b2 = (const float*)d_in[25];
    const float* ap_W0 = (const float*)d_in[26];
    const float* ap_b0 = (const float*)d_in[27];
    const float* ap_W1 = (const float*)d_in[28];
    const float* ap_b1 = (const float*)d_in[29];
    const float* ap_W2 = (const float*)d_in[30];
    const float* ap_b2 = (const float*)d_in[31];
    float* out = (float*)d_out;

    static int smem_set = 0;
    if (!smem_set) {
        cudaFuncSetAttribute(k_induct, cudaFuncAttributeMaxDynamicSharedMemorySize,
                             IND_SMEM_FLOATS * 4);
        smem_set = 1;
    }

    k_embed<<<322, 256>>>(nodes1, nodes2, edges1, edges2,
                          W_emb_node, b_emb_node, W_emb_edge, b_emb_edge,
                          receivers1, receivers2);
    int ib = 0;
    for (int s = 0; s < 3; s++) {
        int ob = 1 - ib;
        k_edge<<<256, 256>>>(s, ib, ob, senders1, receivers1, senders2, receivers2,
                             W_gn_edge, b_gn_edge);
        k_node<<<128, 128>>>(s, ib, ob, (s == 2) ? 1 : 0, W_gn_node, b_gn_node,
                             ap_W0, ap_b0, ap_W1, ap_b1, ap_W2, ap_b2, pp_W0);
        ib = ob;
    }
    k_pair<<<256, 256>>>(pp_b0, pp_W1, pp_b1, pp_W2, pp_b2, mp, coords1, coords2);
    k_induct<<<BB, 1024, IND_SMEM_FLOATS * 4>>>(dist, out);
}

// round 13
// speedup vs baseline: 1.0296x; 1.0296x over previous
#include <cuda_runtime.h>
#include <math.h>

#define NN   128
#define NE   512
#define HID  64
#define BB   64
#define NP   16384     // NN*NN
#define SMEAR (-0.39f)
#define FEPS  1e-6f

// ---------------- device scratch (no allocation allowed) ----------------
__device__ float  g_n[2][2][NN][HID];     // [pingpong][mol][node][feat]
__device__ float  g_e[2][2][NE][HID];     // [pingpong][mol][edge][feat]
__device__ int    g_h[2][NN];
__device__ int    g_cnt[2][NN];
__device__ short  g_elist[2][NN][NE];
__device__ float  g_ap[2][NN][5];         // a_d, pol, K, dq, a_e
__device__ float  g_u[2][NN][HID];        // feats @ ppW0[0:64]
__device__ float  g_v[2][NN][HID];        // feats @ ppW0[64:128]
__device__ float  g_pp[11][NP];           // C6,C8,C10,r3,r4,r5,Act,bct,bd,be,Kp
__device__ float4 g_cpack[2][BB][NN];     // (cx,cy,cz,q)
__device__ float  g_qe[2][BB][NN];

// mila(x) = x * tanh(softplus(x-1)) = x * (1 - 2/((1+e^{x-1})^2 + 1))  (exact)
__device__ __forceinline__ float milaf(float x) {
    float t = expf(x - 1.0f);
    float a = 1.0f + t;
    float d = fmaf(a, a, 1.0f);
    return x * (1.0f - __fdividef(2.0f, d));
}
__device__ __forceinline__ float sspf(float x) {
    return fmaxf(x, 0.0f) + log1pf(expf(-fabsf(x))) + 0.001f;
}
__device__ __forceinline__ float wred(float v) {
    #pragma unroll
    for (int o = 16; o; o >>= 1) v += __shfl_xor_sync(0xffffffffu, v, o);
    return v;
}

// ---------------- GNN: embed + CSR build fused ----------------
__global__ void __launch_bounds__(256) k_embed(
                        const float* __restrict__ nodes1, const float* __restrict__ nodes2,
                        const float* __restrict__ edges1, const float* __restrict__ edges2,
                        const float* __restrict__ Wn, const float* __restrict__ bn,
                        const float* __restrict__ We, const float* __restrict__ be_,
                        const int* __restrict__ rcv1, const int* __restrict__ rcv2) {
    if (blockIdx.x == 321) {           // CSR build section
        int t = threadIdx.x;           // 256 threads
        int m = t >> 7, node = t & 127;
        const int* rcv = m ? rcv2 : rcv1;
        int c = 0;
        for (int e = 0; e < NE; e++) {
            if (rcv[e] == node) g_elist[m][node][c++] = (short)e;
        }
        g_cnt[m][node] = c;
        return;
    }
    int g = blockIdx.x * 256 + threadIdx.x;   // 82176 total
    if (g < 2 * NN * HID) {
        int m = g / (NN * HID);
        int r = g % (NN * HID);
        int i = r / HID, o = r % HID;
        const float* nd = m ? nodes2 : nodes1;
        float acc = bn[o];
        #pragma unroll
        for (int k = 0; k < 16; k++) acc = fmaf(nd[i * 16 + k], __ldg(Wn + k * HID + o), acc);
        g_n[0][m][i][o] = milaf(acc);
    } else if (g < 2 * NN * HID + 2 * NE * HID) {
        int r = g - 2 * NN * HID;
        int m = r / (NE * HID);
        r %= NE * HID;
        int ei = r / HID, o = r % HID;
        const float* ed = m ? edges2 : edges1;
        float acc = be_[o];
        #pragma unroll
        for (int k = 0; k < 8; k++) acc = fmaf(ed[ei * 8 + k], __ldg(We + k * HID + o), acc);
        g_e[0][m][ei][o] = milaf(acc);
    } else {
        int r = g - (2 * NN * HID + 2 * NE * HID);   // < 256
        int m = r >> 7, i = r & 127;
        const float* nd = m ? nodes2 : nodes1;
        float v0 = nd[i * 16];
        float mx = -1e30f;
        #pragma unroll
        for (int k = 1; k < 16; k++) mx = fmaxf(mx, nd[i * 16 + k]);
        g_h[m][i] = (v0 >= mx) ? 1 : 0;
    }
}

// ---------------- edge update: 256 blocks, 1 item/thread, 3 acc chains ----------------
__global__ void __launch_bounds__(256) k_edge(int s, int ib, int ob,
                       const int* __restrict__ snd1, const int* __restrict__ rcv1,
                       const int* __restrict__ snd2, const int* __restrict__ rcv2,
                       const float* __restrict__ Wge, const float* __restrict__ bge) {
    __shared__ float sW[192 * 64];           // 48KB: Wge[s] natural layout [k*64+o]
    const float4* Wv = (const float4*)(Wge + s * 192 * 64);
    #pragma unroll
    for (int k = 0; k < 12; k++)             // vectorized preload: 12 LDG.128/thread
        ((float4*)sW)[threadIdx.x + 256 * k] = Wv[threadIdx.x + 256 * k];
    __syncthreads();
    int g = blockIdx.x * 256 + threadIdx.x;  // 65536 total, grid 256
    int m = g >> 15;
    int r = g & 32767;
    int e = r >> 6, o = r & 63;
    const int* snd = m ? snd2 : snd1;
    const int* rcv = m ? rcv2 : rcv1;
    int sidx = snd[e], ridx = rcv[e];
    const float4* er = (const float4*)&g_e[ib][m][e][0];
    const float4* nr = (const float4*)&g_n[ib][m][ridx][0];
    const float4* ns = (const float4*)&g_n[ib][m][sidx][0];
    float acc1 = bge[s * 64 + o];            // 3 independent chains for ILP
    float acc2 = 0.0f;
    float acc3 = 0.0f;
    #pragma unroll 4
    for (int c = 0; c < 16; c++) {
        float4 ev = er[c], rv = nr[c], sv = ns[c];
        int k4 = 4 * c;
        acc1 = fmaf(ev.x, sW[(k4 + 0) * 64 + o], acc1);
        acc2 = fmaf(rv.x, sW[(64 + k4 + 0) * 64 + o], acc2);
        acc3 = fmaf(sv.x, sW[(128 + k4 + 0) * 64 + o], acc3);
        acc1 = fmaf(ev.y, sW[(k4 + 1) * 64 + o], acc1);
        acc2 = fmaf(rv.y, sW[(64 + k4 + 1) * 64 + o], acc2);
        acc3 = fmaf(sv.y, sW[(128 + k4 + 1) * 64 + o], acc3);
        acc1 = fmaf(ev.z, sW[(k4 + 2) * 64 + o], acc1);
        acc2 = fmaf(rv.z, sW[(64 + k4 + 2) * 64 + o], acc2);
        acc3 = fmaf(sv.z, sW[(128 + k4 + 2) * 64 + o], acc3);
        acc1 = fmaf(ev.w, sW[(k4 + 3) * 64 + o], acc1);
        acc2 = fmaf(rv.w, sW[(64 + k4 + 3) * 64 + o], acc2);
        acc3 = fmaf(sv.w, sW[(128 + k4 + 3) * 64 + o], acc3);
    }
    g_e[ob][m][e][o] = milaf(acc1 + acc2 + acc3);
}

// ---------------- node update: 64 blocks x 256 threads, smem weights, fused gather+post ----------------
__global__ void __launch_bounds__(256) k_node(int s, int ib, int ob, int last,
                       const float* __restrict__ Wgn, const float* __restrict__ bgn,
                       const float* __restrict__ apW0, const float* __restrict__ apb0,
                       const float* __restrict__ apW1, const float* __restrict__ apb1,
                       const float* __restrict__ apW2, const float* __restrict__ apb2,
                       const float* __restrict__ ppW0) {
    __shared__ float sW[128 * 64];            // 32KB, layout [k*64+o]
    __shared__ float sagg[4][64];
    __shared__ float sf[256], sh1[256], sh2[256];
    int tid = threadIdx.x;
    int g = blockIdx.x * 256 + tid;           // 16384 total, grid 64
    int m = g >> 13;
    int r = g & 8191;
    int i = r >> 6, o = r & 63;
    int nl = tid >> 6;                        // node slot within block (0..3)
    // fused segment-sum: gather this node's aggregated edge vector component o
    int cnt = g_cnt[m][i];
    float agg = 0.0f;
    for (int c = 0; c < cnt; c++) agg += g_e[ob][m][g_elist[m][i][c]][o];
    // vectorized weight preload overlaps gather latency: 8 LDG.128/thread
    const float4* Wv = (const float4*)(Wgn + s * 128 * 64);
    #pragma unroll
    for (int k = 0; k < 8; k++)
        ((float4*)sW)[tid + 256 * k] = Wv[tid + 256 * k];
    sagg[nl][o] = agg;
    __syncthreads();
    const float4* nr = (const float4*)&g_n[ib][m][i][0];
    const float4* ar = (const float4*)&sagg[nl][0];
    float acc1 = bgn[s * 64 + o];             // 2 independent chains for ILP
    float acc2 = 0.0f;
    #pragma unroll 4
    for (int c = 0; c < 16; c++) {
        float4 nv = nr[c], av = ar[c];
        int k4 = 4 * c;
        acc1 = fmaf(nv.x, sW[(k4 + 0) * 64 + o], acc1);
        acc2 = fmaf(av.x, sW[(64 + k4 + 0) * 64 + o], acc2);
        acc1 = fmaf(nv.y, sW[(k4 + 1) * 64 + o], acc1);
        acc2 = fmaf(av.y, sW[(64 + k4 + 1) * 64 + o], acc2);
        acc1 = fmaf(nv.z, sW[(k4 + 2) * 64 + o], acc1);
        acc2 = fmaf(av.z, sW[(64 + k4 + 2) * 64 + o], acc2);
        acc1 = fmaf(nv.w, sW[(k4 + 3) * 64 + o], acc1);
        acc2 = fmaf(av.w, sW[(64 + k4 + 3) * 64 + o], acc2);
    }
    float val = milaf(acc1 + acc2);
    g_n[ob][m][i][o] = val;
    if (last) {   // fused per-node post: atom-props MLP + pair-layer-0 factorization
        sf[tid] = val;
        __syncthreads();
        const float* f = &sf[nl * 64];
        float a = apb0[o], su = 0.0f, sv = 0.0f;
        #pragma unroll 8
        for (int k = 0; k < 64; k++) {
            float fk = f[k];
            a  = fmaf(fk, __ldg(apW0 + k * 64 + o), a);
            su = fmaf(fk, __ldg(ppW0 + k * 64 + o), su);
            sv = fmaf(fk, __ldg(ppW0 + (64 + k) * 64 + o), sv);
        }
        sh1[tid] = milaf(a);
        g_u[m][i][o] = su;
        g_v[m][i][o] = sv;
        __syncthreads();
        float a1 = apb1[o];
        const float* h1 = &sh1[nl * 64];
        #pragma unroll 8
        for (int k = 0; k < 64; k++) a1 = fmaf(h1[k], __ldg(apW1 + k * 64 + o), a1);
        sh2[tid] = milaf(a1);
        __syncthreads();
        if (o < 5) {
            float a2 = apb2[o];
            const float* h2 = &sh2[nl * 64];
            for (int k = 0; k < 64; k++) a2 = fmaf(h2[k], __ldg(apW2 + k * 5 + o), a2);
            g_ap[m][i][o] = sspf(a2);
        }
    }
}

// ---------------- pair MLP (warp per pair) + fold-in of per-(b,node) prep ----------------
__global__ void __launch_bounds__(256) k_pair(
                       const float* __restrict__ ppb0, const float* __restrict__ ppW1,
                       const float* __restrict__ ppb1, const float* __restrict__ ppW2,
                       const float* __restrict__ ppb2, const float* __restrict__ mp,
                       const float* __restrict__ coords1, const float* __restrict__ coords2) {
    __shared__ float sW1[4096];
    __shared__ float sW2[320];
    __shared__ float sb0[64], sb1[64], sb2[8];
    __shared__ float sh[8][64];
    int tid = threadIdx.x;
    int gq = blockIdx.x * 256 + tid;
    if (gq < 2 * BB * NN) {
        int m = gq >> 13;
        int r = gq & 8191;
        int b = r >> 7, n = r & 127;
        float q = mp[(m * BB + b) * NN + n];
        float dq = g_ap[m][n][3];
        float qe = g_h[m][n] ? (1.0f - q) : (2.0f + dq - q);
        g_qe[m][b][n] = qe;
        const float* cc = (m ? coords2 : coords1) + (b * NN + n) * 3;
        g_cpack[m][b][n] = make_float4(cc[0], cc[1], cc[2], q);
    }
    for (int k = tid; k < 4096; k += 256) sW1[k] = ppW1[k];
    for (int k = tid; k < 320; k += 256) sW2[k] = ppW2[k];
    if (tid < 64) { sb0[tid] = ppb0[tid]; sb1[tid] = ppb1[tid]; }
    if (tid < 5)  sb2[tid] = ppb2[tid];
    __syncthreads();
    int warp = tid >> 5, lane = tid & 31;
    float* hw = sh[warp];
    for (int t = 0; t < 8; t++) {
        int p = blockIdx.x * 64 + warp * 8 + t;
        int i = p >> 7, j = p & 127;
        float pr0 = 0, pr1 = 0, pr2 = 0, pr3 = 0, pr4 = 0;
        #pragma unroll
        for (int d = 0; d < 2; d++) {
            const float* U = d ? g_u[1][j] : g_u[0][i];
            const float* V = d ? g_v[0][i] : g_v[1][j];
            float2 uu = *(const float2*)(U + 2 * lane);
            float2 vv = *(const float2*)(V + 2 * lane);
            float h0 = milaf(uu.x + vv.x + sb0[2 * lane]);
            float h1 = milaf(uu.y + vv.y + sb0[2 * lane + 1]);
            __syncwarp();
            hw[2 * lane] = h0; hw[2 * lane + 1] = h1;
            __syncwarp();
            float a0 = sb1[2 * lane], a1 = sb1[2 * lane + 1];
            #pragma unroll 8
            for (int k = 0; k < 64; k++) {
                float hk = hw[k];
                float2 w = *(const float2*)(sW1 + k * 64 + 2 * lane);
                a0 = fmaf(hk, w.x, a0);
                a1 = fmaf(hk, w.y, a1);
            }
            float g0 = milaf(a0), g1 = milaf(a1);
            const float* w2a = sW2 + (2 * lane) * 5;
            const float* w2b = sW2 + (2 * lane + 1) * 5;
            float p0 = g0 * w2a[0] + g1 * w2b[0];
            float p1 = g0 * w2a[1] + g1 * w2b[1];
            float p2 = g0 * w2a[2] + g1 * w2b[2];
            float p3 = g0 * w2a[3] + g1 * w2b[3];
            float p4 = g0 * w2a[4] + g1 * w2b[4];
            p0 = wred(p0); p1 = wred(p1); p2 = wred(p2); p3 = wred(p3); p4 = wred(p4);
            pr0 += sspf(p0 + sb2[0]);
            pr1 += sspf(p1 + sb2[1]);
            pr2 += sspf(p2 + sb2[2]);
            pr3 += sspf(p3 + sb2[3]);
            pr4 += sspf(p4 + sb2[4]);
        }
        if (lane == 0) {
            float C6 = pr0, C8 = pr1, C10 = pr2, Act = pr3, bct = pr4;
            float r02 = C8 / (C6 + FEPS);
            float r3 = r02 * r02 * r02, r4 = r3 * r02, r5 = r4 * r02;
            float bd = sqrtf(g_ap[0][i][0] * g_ap[1][j][0]);
            float be = sqrtf(g_ap[0][i][4] * g_ap[1][j][4]);
            float Kp = g_ap[0][i][2] * g_ap[1][j][2];
            g_pp[0][p] = C6;  g_pp[1][p] = C8;  g_pp[2][p] = C10;
            g_pp[3][p] = r3;  g_pp[4][p] = r4;  g_pp[5][p] = r5;
            g_pp[6][p] = Act; g_pp[7][p] = bct; g_pp[8][p] = bd;
            g_pp[9][p] = be;  g_pp[10][p] = Kp;
        }
    }
}

// ---------------- mega-fused induction + energy: one block per batch b ----------------
#define IND_SMEM_FLOATS (33024 + 6*128*4 + 256 + 4*256*4)

__global__ void __launch_bounds__(1024, 1) k_induct(const float* __restrict__ dist,
                                                    float* __restrict__ out) {
    extern __shared__ float smem[];
    float*  c3s = smem;
    float*  c5s = smem + 16512;
    float4* cpA = (float4*)(smem + 33024);
    float4* cpB = cpA + 128;
    float4* muA = cpB + 128;
    float4* muB = muA + 128;
    float4* e0A = muB + 128;
    float4* e0B = e0A + 128;
    float*  qeS = (float*)(e0B + 128);
    float4* part = (float4*)(qeS + 256);
    float*  ired = c3s;                       // safe reuse after iterations

    int b = blockIdx.x;
    int tid = threadIdx.x;                    // 1024 threads

    // ---- stage per-atom data ----
    if (tid < 256) {
        int m = tid >> 7, n = tid & 127;
        float4 cp = g_cpack[m][b][n];
        (m ? cpB : cpA)[n] = cp;
        qeS[tid] = g_qe[m][b][n];
        float pol = g_ap[m][n][1];
        (m ? e0B : e0A)[n] = make_float4(0.0f, 0.0f, 0.0f, pol);
    }
    __syncthreads();

    // ---- compute c3/c5 coefficients (16 pairs per thread, coalesced) ----
    #pragma unroll
    for (int k = 0; k < 16; k++) {
        int p = tid + 1024 * k;
        int i = p >> 7, j = p & 127;
        float R = dist[b * NP + p];
        float au = sqrtf(e0A[i].w * e0B[j].w) + FEPS;
        float R2 = R * R;
        float r3raw = R2 * R;
        float u3 = __fdividef(r3raw, au);
        float exu = expf(SMEAR * u3);
        float lam3 = 1.0f - exu;
        float lam5 = 1.0f - (1.0f - SMEAR * u3) * exu;
        c3s[i * 129 + j] = __fdividef(lam3, r3raw + FEPS);
        c5s[i * 129 + j] = __fdividef(3.0f * lam5, R2 * r3raw + FEPS);
    }
    __syncthreads();

    // ---- warp mapping: 8 row-groups x 4 col-slices ----
    int w = tid >> 5, lane = tid & 31;
    int gg = w & 7;                           // row group (32 rows)
    int slice = w >> 3;                       // col slice (32 cols)
    int rrow = gg * 32 + lane;                // 0..255
    int mol = rrow >> 7;
    int n = rrow & 127;
    float4 cs = mol ? cpB[n] : cpA[n];
    const float4* cop = mol ? cpA : cpB;
    int c0 = slice * 32;

    // ---- E0 pass:  E0_row = cs*Σ(q c3) − Σ(q c3 co) ----
    {
        float sk = 0, sx = 0, sy = 0, sz = 0;
        #pragma unroll 4
        for (int c = 0; c < 32; c++) {
            int oth = c0 + c;
            float c3 = mol ? c3s[oth * 129 + n] : c3s[n * 129 + oth];
            float4 co = cop[oth];
            float wq = co.w * c3;
            sk += wq;
            sx = fmaf(wq, co.x, sx);
            sy = fmaf(wq, co.y, sy);
            sz = fmaf(wq, co.z, sz);
        }
        part[slice * 256 + rrow] = make_float4(fmaf(cs.x, sk, -sx),
                                               fmaf(cs.y, sk, -sy),
                                               fmaf(cs.z, sk, -sz), 0.0f);
    }
    __syncthreads();
    if (tid < 256) {
        float4 a0 = part[tid], a1 = part[256 + tid], a2 = part[512 + tid], a3 = part[768 + tid];
        float ex0 = a0.x + a1.x + a2.x + a3.x;
        float ey0 = a0.y + a1.y + a2.y + a3.y;
        float ez0 = a0.z + a1.z + a2.z + a3.z;
        int m = tid >> 7, nn = tid & 127;
        float4* e0p = m ? e0B : e0A;
        float pol = e0p[nn].w;
        e0p[nn] = make_float4(ex0, ey0, ez0, pol);
        float mux = pol * ex0, muy = pol * ey0, muz = pol * ez0;
        float4 cc = m ? cpB[nn] : cpA[nn];
        float dcm = cc.x * mux + cc.y * muy + cc.z * muz;
        (m ? muB : muA)[nn] = make_float4(mux, muy, muz, dcm);
    }
    __syncthreads();

    // ---- 8 fixed-point iterations, mu resident in smem ----
    const float4* mop = mol ? muA : muB;
    for (int it = 0; it < 8; it++) {
        float sk = 0, sx = 0, sy = 0, sz = 0, tx = 0, ty = 0, tz = 0;
        #pragma unroll 4
        for (int c = 0; c < 32; c++) {
            int oth = c0 + c;
            float c3, c5;
            if (mol) { c3 = c3s[oth * 129 + n]; c5 = c5s[oth * 129 + n]; }
            else     { c3 = c3s[n * 129 + oth]; c5 = c5s[n * 129 + oth]; }
            float4 mo = mop[oth];
            float4 co = cop[oth];
            float rm = fmaf(cs.x, mo.x, fmaf(cs.y, mo.y, fmaf(cs.z, mo.z, -mo.w)));
            float k5 = c5 * rm;
            sk += k5;
            sx = fmaf(k5, co.x, sx);
            sy = fmaf(k5, co.y, sy);
            sz = fmaf(k5, co.z, sz);
            tx = fmaf(c3, mo.x, tx);
            ty = fmaf(c3, mo.y, ty);
            tz = fmaf(c3, mo.z, tz);
        }
        part[slice * 256 + rrow] = make_float4(fmaf(cs.x, sk, -sx) - tx,
                                               fmaf(cs.y, sk, -sy) - ty,
                                               fmaf(cs.z, sk, -sz) - tz, 0.0f);
        __syncthreads();
        if (tid < 256) {
            float4 a0 = part[tid], a1 = part[256 + tid], a2 = part[512 + tid], a3 = part[768 + tid];
            float ax = a0.x + a1.x + a2.x + a3.x;
            float ay = a0.y + a1.y + a2.y + a3.y;
            float az = a0.z + a1.z + a2.z + a3.z;
            int m = tid >> 7, nn = tid & 127;
            float4 e0 = (m ? e0B : e0A)[nn];
            float4 mo = (m ? muB : muA)[nn];
            float pol = e0.w;
            float fx = e0.x + ax, fy = e0.y + ay, fz = e0.z + az;
            float mux = fmaf(0.75f * pol, fx, 0.25f * mo.x);
            float muy = fmaf(0.75f * pol, fy, 0.25f * mo.y);
            float muz = fmaf(0.75f * pol, fz, 0.25f * mo.z);
            float4 cc = m ? cpB[nn] : cpA[nn];
            float dcm = cc.x * mux + cc.y * muy + cc.z * muz;
            (m ? muB : muA)[nn] = make_float4(mux, muy, muz, dcm);
        }
        __syncthreads();
    }

    // ---- energy terms (16 pairs per thread, coalesced) ----
    float es_a = 0, ex_a = 0, dsp_a = 0, ct_a = 0;
    #pragma unroll 4
    for (int k = 0; k < 16; k++) {
        int p = tid + 1024 * k;
        int i = p >> 7, j = p & 127;
        float R = dist[b * NP + p];
        float C6  = g_pp[0][p], C8  = g_pp[1][p], C10 = g_pp[2][p];
        float r3  = g_pp[3][p], r4  = g_pp[4][p], r5  = g_pp[5][p];
        float Act = g_pp[6][p], bct = g_pp[7][p];
        float bd  = g_pp[8][p], be  = g_pp[9][p], Kp = g_pp[10][p];
        float4 c1p = cpA[i];
        float4 c2p = cpB[j];
        float4 m1 = muA[i];
        float4 m2 = muB[j];
        float B0 = __fdividef(1.0f, R + FEPS);
        float ebd = expf(-bd * R);
        es_a += c1p.w * c2p.w * (1.0f - fmaf(0.5f * bd, R, 1.0f) * ebd) * B0;
        ct_a += Act * expf(-bct * R);
        float R2 = R * R;
        if (R2 < 2500.0f) {
            float R6 = R2 * R2 * R2;
            float R8 = R6 * R2;
            float R10 = R8 * R2;
            dsp_a -= __fdividef(C6, R6 + r3) + __fdividef(C8, R8 + r4) + __fdividef(C10, R10 + r5);
        }
        float rhx = (c2p.x - c1p.x) * B0;
        float rhy = (c2p.y - c1p.y) * B0;
        float rhz = (c2p.z - c1p.z) * B0;
        float proj = (m1.x - m2.x) * rhx + (m1.y - m2.y) * rhy + (m1.z - m2.z) * rhz;
        ex_a += Kp * qeS[i] * qeS[128 + j] * (1.0f + proj) * expf(-be * R) * B0;
    }
    float iev = 0.0f;
    if (tid < 256) {
        int m = tid >> 7, nn = tid & 127;
        float4 mo = (m ? muB : muA)[nn];
        float4 e0 = (m ? e0B : e0A)[nn];
        iev = mo.x * e0.x + mo.y * e0.y + mo.z * e0.z;
    }
    __syncthreads();                          // all c3s/part reads complete
    part[tid] = make_float4(es_a, ex_a, dsp_a, ct_a);
    ired[tid] = iev;
    __syncthreads();
    for (int s = 512; s; s >>= 1) {
        if (tid < s) {
            float4 a = part[tid], c = part[tid + s];
            part[tid] = make_float4(a.x + c.x, a.y + c.y, a.z + c.z, a.w + c.w);
            ired[tid] += ired[tid + s];
        }
        __syncthreads();
    }
    if (tid == 0) {
        float4 a = part[0];
        float in_t = -0.5f * ired[0] - a.w;
        out[b]        = a.y + a.z + a.x + in_t;
        out[64 + b]   = a.x;
        out[128 + b]  = in_t;
        out[192 + b]  = a.y;
        out[256 + b]  = a.z;
    }
}

// ---------------- launch ----------------
extern "C" void kernel_launch(void* const* d_in, const int* in_sizes, int n_in,
                              void* d_out, int out_size) {
    const float* nodes1    = (const float*)d_in[0];
    const float* edges1    = (const float*)d_in[1];
    const int*   senders1  = (const int*)d_in[2];
    const int*   receivers1= (const int*)d_in[3];
    const float* nodes2    = (const float*)d_in[4];
    const float* edges2    = (const float*)d_in[5];
    const int*   senders2  = (const int*)d_in[6];
    const int*   receivers2= (const int*)d_in[7];
    const float* coords1   = (const float*)d_in[8];
    const float* coords2   = (const float*)d_in[9];
    const float* dist;
    const float* mp;
    if (in_sizes[10] == 2 * BB * NN) {        // multipoles came first
        mp   = (const float*)d_in[10];
        dist = (const float*)d_in[11];
    } else {                                  // distance_matrices first (setup order)
        dist = (const float*)d_in[10];
        mp   = (const float*)d_in[11];
    }
    const float* W_emb_node = (const float*)d_in[12];
    const float* b_emb_node = (const float*)d_in[13];
    const float* W_emb_edge = (const float*)d_in[14];
    const float* b_emb_edge = (const float*)d_in[15];
    const float* W_gn_edge  = (const float*)d_in[16];
    const float* b_gn_edge  = (const float*)d_in[17];
    const float* W_gn_node  = (const float*)d_in[18];
    const float* b_gn_node  = (const float*)d_in[19];
    const float* pp_W0 = (const float*)d_in[20];
    const float* pp_b0 = (const float*)d_in[21];
    const float* pp_W1 = (const float*)d_in[22];
    const float* pp_b1 = (const float*)d_in[23];
    const float* pp_W2 = (const float*)d_in[24];
    const float* pp_b2 = (const float*)d_in[25];
    const float* ap_W0 = (const float*)d_in[26];
    const float* ap_b0 = (const float*)d_in[27];
    const float* ap_W1 = (const float*)d_in[28];
    const float* ap_b1 = (const float*)d_in[29];
    const float* ap_W2 = (const float*)d_in[30];
    const float* ap_b2 = (const float*)d_in[31];
    float* out = (float*)d_out;

    static int smem_set = 0;
    if (!smem_set) {
        cudaFuncSetAttribute(k_induct, cudaFuncAttributeMaxDynamicSharedMemorySize,
                             IND_SMEM_FLOATS * 4);
        smem_set = 1;
    }

    k_embed<<<322, 256>>>(nodes1, nodes2, edges1, edges2,
                          W_emb_node, b_emb_node, W_emb_edge, b_emb_edge,
                          receivers1, receivers2);
    int ib = 0;
    for (int s = 0; s < 3; s++) {
        int ob = 1 - ib;
        k_edge<<<256, 256>>>(s, ib, ob, senders1, receivers1, senders2, receivers2,
                             W_gn_edge, b_gn_edge);
        k_node<<<64, 256>>>(s, ib, ob, (s == 2) ? 1 : 0, W_gn_node, b_gn_node,
                            ap_W0, ap_b0, ap_W1, ap_b1, ap_W2, ap_b2, pp_W0);
        ib = ob;
    }
    k_pair<<<256, 256>>>(pp_b0, pp_W1, pp_b1, pp_W2, pp_b2, mp, coords1, coords2);
    k_induct<<<BB, 1024, IND_SMEM_FLOATS * 4>>>(dist, out);
}

// round 14
// speedup vs baseline: 1.3181x; 1.2802x over previous
#include <cuda_runtime.h>
#include <math.h>

#define NN   128
#define NE   512
#define HID  64
#define BB   64
#define NP   16384     // NN*NN
#define SMEAR (-0.39f)
#define FEPS  1e-6f
#define NBLK 128       // persistent grid: <= SM count, all resident

// ---------------- device scratch (no allocation allowed) ----------------
__device__ float  g_n[2][2][NN][HID];     // [pingpong][mol][node][feat]
__device__ float  g_e[2][2][NE][HID];     // [pingpong][mol][edge][feat]
__device__ int    g_h[2][NN];
__device__ int    g_cnt[2][NN];
__device__ short  g_elist[2][NN][NE];
__device__ float  g_ap[2][NN][5];         // a_d, pol, K, dq, a_e
__device__ float  g_u[2][NN][HID];        // feats @ ppW0[0:64]
__device__ float  g_v[2][NN][HID];        // feats @ ppW0[64:128]
__device__ float  g_pp[11][NP];           // C6,C8,C10,r3,r4,r5,Act,bct,bd,be,Kp
__device__ float4 g_cpack[2][BB][NN];     // (cx,cy,cz,q)
__device__ float  g_qe[2][BB][NN];
__device__ int           g_bar_count;     // zero-init; returns to 0 after each barrier
__device__ volatile int  g_bar_gen;       // monotonically increasing generation

// mila(x) = x * tanh(softplus(x-1)) = x * (1 - 2/((1+e^{x-1})^2 + 1))  (exact)
__device__ __forceinline__ float milaf(float x) {
    float t = expf(x - 1.0f);
    float a = 1.0f + t;
    float d = fmaf(a, a, 1.0f);
    return x * (1.0f - __fdividef(2.0f, d));
}
__device__ __forceinline__ float sspf(float x) {
    return fmaxf(x, 0.0f) + log1pf(expf(-fabsf(x))) + 0.001f;
}
__device__ __forceinline__ float wred(float v) {
    #pragma unroll
    for (int o = 16; o; o >>= 1) v += __shfl_xor_sync(0xffffffffu, v, o);
    return v;
}

// sense-reversing grid barrier. All NBLK blocks resident (NBLK <= #SM).
// __threadfence() (gpu scope) flushes L1D on sm_103a -> cross-block visibility.
__device__ __forceinline__ void gridbar() {
    __threadfence();
    __syncthreads();
    if (threadIdx.x == 0) {
        int gen = g_bar_gen;
        if (atomicAdd(&g_bar_count, 1) == NBLK - 1) {
            g_bar_count = 0;
            __threadfence();
            g_bar_gen = gen + 1;
        } else {
            while (g_bar_gen == gen) __nanosleep(64);
        }
    }
    __syncthreads();
    __threadfence();
}

// ================= persistent GNN + pair mega-kernel =================
__global__ void __launch_bounds__(256) k_gnn(
        const float* __restrict__ nodes1, const float* __restrict__ nodes2,
        const float* __restrict__ edges1, const float* __restrict__ edges2,
        const int* __restrict__ snd1, const int* __restrict__ rcv1,
        const int* __restrict__ snd2, const int* __restrict__ rcv2,
        const float* __restrict__ Wn, const float* __restrict__ bn,
        const float* __restrict__ We, const float* __restrict__ be_,
        const float* __restrict__ Wge, const float* __restrict__ bge,
        const float* __restrict__ Wgn, const float* __restrict__ bgn,
        const float* __restrict__ apW0, const float* __restrict__ apb0,
        const float* __restrict__ apW1, const float* __restrict__ apb1,
        const float* __restrict__ apW2, const float* __restrict__ apb2,
        const float* __restrict__ ppW0, const float* __restrict__ ppb0,
        const float* __restrict__ ppW1, const float* __restrict__ ppb1,
        const float* __restrict__ ppW2, const float* __restrict__ ppb2,
        const float* __restrict__ mp,
        const float* __restrict__ coords1, const float* __restrict__ coords2) {
    __shared__ float sbuf[12288];            // 48KB, reused across phases
    int tid = threadIdx.x;
    int bid = blockIdx.x;

    // ---------- P0: embed (127 blocks) + CSR build (block 127) ----------
    if (bid == NBLK - 1) {
        int m = tid >> 7, node = tid & 127;
        const int* rcv = m ? rcv2 : rcv1;
        int c = 0;
        for (int e = 0; e < NE; e++) {
            if (rcv[e] == node) g_elist[m][node][c++] = (short)e;
        }
        g_cnt[m][node] = c;
    } else {
        for (int g = bid * 256 + tid; g < 2 * NN * HID + 2 * NE * HID + 2 * NN;
             g += (NBLK - 1) * 256) {
            if (g < 2 * NN * HID) {
                int m = g / (NN * HID);
                int r = g % (NN * HID);
                int i = r / HID, o = r % HID;
                const float* nd = m ? nodes2 : nodes1;
                float acc = bn[o];
                #pragma unroll
                for (int k = 0; k < 16; k++)
                    acc = fmaf(nd[i * 16 + k], __ldg(Wn + k * HID + o), acc);
                g_n[0][m][i][o] = milaf(acc);
            } else if (g < 2 * NN * HID + 2 * NE * HID) {
                int r = g - 2 * NN * HID;
                int m = r / (NE * HID);
                r %= NE * HID;
                int ei = r / HID, o = r % HID;
                const float* ed = m ? edges2 : edges1;
                float acc = be_[o];
                #pragma unroll
                for (int k = 0; k < 8; k++)
                    acc = fmaf(ed[ei * 8 + k], __ldg(We + k * HID + o), acc);
                g_e[0][m][ei][o] = milaf(acc);
            } else {
                int r = g - (2 * NN * HID + 2 * NE * HID);
                int m = r >> 7, i = r & 127;
                const float* nd = m ? nodes2 : nodes1;
                float v0 = nd[i * 16];
                float mx = -1e30f;
                #pragma unroll
                for (int k = 1; k < 16; k++) mx = fmaxf(mx, nd[i * 16 + k]);
                g_h[m][i] = (v0 >= mx) ? 1 : 0;
            }
        }
    }
    gridbar();

    // ---------- message-passing steps ----------
    int ib = 0;
    for (int s = 0; s < 3; s++) {
        int ob = 1 - ib;

        // ----- edge phase: all 128 blocks, 2 chunks of 256 each -----
        {
            float* sW = sbuf;                  // 192*64 floats
            const float4* Wv = (const float4*)(Wge + s * 192 * 64);
            #pragma unroll
            for (int k = 0; k < 12; k++)
                ((float4*)sW)[tid + 256 * k] = Wv[tid + 256 * k];
            __syncthreads();
            #pragma unroll
            for (int ch = 0; ch < 2; ch++) {
                int g = bid * 256 + tid + ch * 32768;   // < 65536
                int m = g >> 15;
                int r = g & 32767;
                int e = r >> 6, o = r & 63;
                const int* snd = m ? snd2 : snd1;
                const int* rcv = m ? rcv2 : rcv1;
                int sidx = snd[e], ridx = rcv[e];
                const float4* er = (const float4*)&g_e[ib][m][e][0];
                const float4* nr = (const float4*)&g_n[ib][m][ridx][0];
                const float4* ns = (const float4*)&g_n[ib][m][sidx][0];
                float acc1 = bge[s * 64 + o];
                float acc2 = 0.0f;
                float acc3 = 0.0f;
                #pragma unroll 4
                for (int c = 0; c < 16; c++) {
                    float4 ev = er[c], rv = nr[c], sv = ns[c];
                    int k4 = 4 * c;
                    acc1 = fmaf(ev.x, sW[(k4 + 0) * 64 + o], acc1);
                    acc2 = fmaf(rv.x, sW[(64 + k4 + 0) * 64 + o], acc2);
                    acc3 = fmaf(sv.x, sW[(128 + k4 + 0) * 64 + o], acc3);
                    acc1 = fmaf(ev.y, sW[(k4 + 1) * 64 + o], acc1);
                    acc2 = fmaf(rv.y, sW[(64 + k4 + 1) * 64 + o], acc2);
                    acc3 = fmaf(sv.y, sW[(128 + k4 + 1) * 64 + o], acc3);
                    acc1 = fmaf(ev.z, sW[(k4 + 2) * 64 + o], acc1);
                    acc2 = fmaf(rv.z, sW[(64 + k4 + 2) * 64 + o], acc2);
                    acc3 = fmaf(sv.z, sW[(128 + k4 + 2) * 64 + o], acc3);
                    acc1 = fmaf(ev.w, sW[(k4 + 3) * 64 + o], acc1);
                    acc2 = fmaf(rv.w, sW[(64 + k4 + 3) * 64 + o], acc2);
                    acc3 = fmaf(sv.w, sW[(128 + k4 + 3) * 64 + o], acc3);
                }
                g_e[ob][m][e][o] = milaf(acc1 + acc2 + acc3);
            }
        }
        gridbar();

        // ----- node phase: blocks 0..63 (4 nodes per block) -----
        if (bid < 64) {
            float* sW   = sbuf;                // 128*64 floats
            float* sagg = sbuf + 8192;         // 256
            float* sf   = sbuf + 8448;         // 256
            float* sh1  = sbuf + 8704;         // 256
            float* sh2  = sbuf + 8960;         // 256
            int g = bid * 256 + tid;           // < 16384
            int m = g >> 13;
            int r = g & 8191;
            int i = r >> 6, o = r & 63;
            int nl = tid >> 6;
            int cnt = g_cnt[m][i];
            float agg = 0.0f;
            for (int c = 0; c < cnt; c++) agg += g_e[ob][m][g_elist[m][i][c]][o];
            const float4* Wv = (const float4*)(Wgn + s * 128 * 64);
            #pragma unroll
            for (int k = 0; k < 8; k++)
                ((float4*)sW)[tid + 256 * k] = Wv[tid + 256 * k];
            sagg[tid] = agg;
            __syncthreads();
            const float4* nr = (const float4*)&g_n[ib][m][i][0];
            const float4* ar = (const float4*)&sagg[nl * 64];
            float acc1 = bgn[s * 64 + o];
            float acc2 = 0.0f;
            #pragma unroll 4
            for (int c = 0; c < 16; c++) {
                float4 nv = nr[c], av = ar[c];
                int k4 = 4 * c;
                acc1 = fmaf(nv.x, sW[(k4 + 0) * 64 + o], acc1);
                acc2 = fmaf(av.x, sW[(64 + k4 + 0) * 64 + o], acc2);
                acc1 = fmaf(nv.y, sW[(k4 + 1) * 64 + o], acc1);
                acc2 = fmaf(av.y, sW[(64 + k4 + 1) * 64 + o], acc2);
                acc1 = fmaf(nv.z, sW[(k4 + 2) * 64 + o], acc1);
                acc2 = fmaf(av.z, sW[(64 + k4 + 2) * 64 + o], acc2);
                acc1 = fmaf(nv.w, sW[(k4 + 3) * 64 + o], acc1);
                acc2 = fmaf(av.w, sW[(64 + k4 + 3) * 64 + o], acc2);
            }
            float val = milaf(acc1 + acc2);
            g_n[ob][m][i][o] = val;
            if (s == 2) {   // fused post: atom props + pair-layer-0 factorization
                sf[tid] = val;
                __syncthreads();
                const float* f = &sf[nl * 64];
                float a = apb0[o], su = 0.0f, sv = 0.0f;
                #pragma unroll 8
                for (int k = 0; k < 64; k++) {
                    float fk = f[k];
                    a  = fmaf(fk, __ldg(apW0 + k * 64 + o), a);
                    su = fmaf(fk, __ldg(ppW0 + k * 64 + o), su);
                    sv = fmaf(fk, __ldg(ppW0 + (64 + k) * 64 + o), sv);
                }
                sh1[tid] = milaf(a);
                g_u[m][i][o] = su;
                g_v[m][i][o] = sv;
                __syncthreads();
                float a1 = apb1[o];
                const float* h1 = &sh1[nl * 64];
                #pragma unroll 8
                for (int k = 0; k < 64; k++)
                    a1 = fmaf(h1[k], __ldg(apW1 + k * 64 + o), a1);
                sh2[tid] = milaf(a1);
                __syncthreads();
                if (o < 5) {
                    float a2 = apb2[o];
                    const float* h2 = &sh2[nl * 64];
                    for (int k = 0; k < 64; k++)
                        a2 = fmaf(h2[k], __ldg(apW2 + k * 5 + o), a2);
                    g_ap[m][i][o] = sspf(a2);
                }
            }
        }
        gridbar();
        ib = ob;
    }

    // ---------- pair phase: all 128 blocks, 128 pairs each ----------
    {
        // prep qe/cpack (blocks 0..63 cover 16384 items) — consumed by k_induct
        int idx = bid * 256 + tid;
        if (idx < 2 * BB * NN) {
            int m = idx >> 13;
            int r = idx & 8191;
            int b = r >> 7, n = r & 127;
            float q = mp[(m * BB + b) * NN + n];
            float dq = g_ap[m][n][3];
            float qe = g_h[m][n] ? (1.0f - q) : (2.0f + dq - q);
            g_qe[m][b][n] = qe;
            const float* cc = (m ? coords2 : coords1) + (b * NN + n) * 3;
            g_cpack[m][b][n] = make_float4(cc[0], cc[1], cc[2], q);
        }
        float* sW1 = sbuf;            // 4096
        float* sW2 = sbuf + 4096;     // 320
        float* sb0 = sbuf + 4416;     // 64
        float* sb1 = sbuf + 4480;     // 64
        float* sb2 = sbuf + 4544;     // 8
        float* shh = sbuf + 4608;     // 8*64
        for (int k = tid; k < 4096; k += 256) sW1[k] = ppW1[k];
        for (int k = tid; k < 320; k += 256) sW2[k] = ppW2[k];
        if (tid < 64) { sb0[tid] = ppb0[tid]; sb1[tid] = ppb1[tid]; }
        if (tid < 5)  sb2[tid] = ppb2[tid];
        __syncthreads();
        int warp = tid >> 5, lane = tid & 31;
        float* hw = shh + warp * 64;
        for (int t = 0; t < 16; t++) {
            int p = bid * 128 + warp * 16 + t;      // < 16384
            int i = p >> 7, j = p & 127;
            float pr0 = 0, pr1 = 0, pr2 = 0, pr3 = 0, pr4 = 0;
            #pragma unroll
            for (int d = 0; d < 2; d++) {
                const float* U = d ? g_u[1][j] : g_u[0][i];
                const float* V = d ? g_v[0][i] : g_v[1][j];
                float2 uu = *(const float2*)(U + 2 * lane);
                float2 vv = *(const float2*)(V + 2 * lane);
                float h0 = milaf(uu.x + vv.x + sb0[2 * lane]);
                float h1 = milaf(uu.y + vv.y + sb0[2 * lane + 1]);
                __syncwarp();
                hw[2 * lane] = h0; hw[2 * lane + 1] = h1;
                __syncwarp();
                float a0 = sb1[2 * lane], a1 = sb1[2 * lane + 1];
                #pragma unroll 8
                for (int k = 0; k < 64; k++) {
                    float hk = hw[k];
                    float2 w = *(const float2*)(sW1 + k * 64 + 2 * lane);
                    a0 = fmaf(hk, w.x, a0);
                    a1 = fmaf(hk, w.y, a1);
                }
                float g0 = milaf(a0), g1 = milaf(a1);
                const float* w2a = sW2 + (2 * lane) * 5;
                const float* w2b = sW2 + (2 * lane + 1) * 5;
                float p0 = g0 * w2a[0] + g1 * w2b[0];
                float p1 = g0 * w2a[1] + g1 * w2b[1];
                float p2 = g0 * w2a[2] + g1 * w2b[2];
                float p3 = g0 * w2a[3] + g1 * w2b[3];
                float p4 = g0 * w2a[4] + g1 * w2b[4];
                p0 = wred(p0); p1 = wred(p1); p2 = wred(p2); p3 = wred(p3); p4 = wred(p4);
                pr0 += sspf(p0 + sb2[0]);
                pr1 += sspf(p1 + sb2[1]);
                pr2 += sspf(p2 + sb2[2]);
                pr3 += sspf(p3 + sb2[3]);
                pr4 += sspf(p4 + sb2[4]);
            }
            if (lane == 0) {
                float C6 = pr0, C8 = pr1, C10 = pr2, Act = pr3, bct = pr4;
                float r02 = C8 / (C6 + FEPS);
                float r3 = r02 * r02 * r02, r4 = r3 * r02, r5 = r4 * r02;
                float bd = sqrtf(g_ap[0][i][0] * g_ap[1][j][0]);
                float be = sqrtf(g_ap[0][i][4] * g_ap[1][j][4]);
                float Kp = g_ap[0][i][2] * g_ap[1][j][2];
                g_pp[0][p] = C6;  g_pp[1][p] = C8;  g_pp[2][p] = C10;
                g_pp[3][p] = r3;  g_pp[4][p] = r4;  g_pp[5][p] = r5;
                g_pp[6][p] = Act; g_pp[7][p] = bct; g_pp[8][p] = bd;
                g_pp[9][p] = be;  g_pp[10][p] = Kp;
            }
        }
    }
}

// ---------------- mega-fused induction + energy: one block per batch b ----------------
#define IND_SMEM_FLOATS (33024 + 6*128*4 + 256 + 4*256*4)

__global__ void __launch_bounds__(1024, 1) k_induct(const float* __restrict__ dist,
                                                    float* __restrict__ out) {
    extern __shared__ float smem[];
    float*  c3s = smem;
    float*  c5s = smem + 16512;
    float4* cpA = (float4*)(smem + 33024);
    float4* cpB = cpA + 128;
    float4* muA = cpB + 128;
    float4* muB = muA + 128;
    float4* e0A = muB + 128;
    float4* e0B = e0A + 128;
    float*  qeS = (float*)(e0B + 128);
    float4* part = (float4*)(qeS + 256);
    float*  ired = c3s;                       // safe reuse after iterations

    int b = blockIdx.x;
    int tid = threadIdx.x;                    // 1024 threads

    if (tid < 256) {
        int m = tid >> 7, n = tid & 127;
        float4 cp = g_cpack[m][b][n];
        (m ? cpB : cpA)[n] = cp;
        qeS[tid] = g_qe[m][b][n];
        float pol = g_ap[m][n][1];
        (m ? e0B : e0A)[n] = make_float4(0.0f, 0.0f, 0.0f, pol);
    }
    __syncthreads();

    #pragma unroll
    for (int k = 0; k < 16; k++) {
        int p = tid + 1024 * k;
        int i = p >> 7, j = p & 127;
        float R = dist[b * NP + p];
        float au = sqrtf(e0A[i].w * e0B[j].w) + FEPS;
        float R2 = R * R;
        float r3raw = R2 * R;
        float u3 = __fdividef(r3raw, au);
        float exu = expf(SMEAR * u3);
        float lam3 = 1.0f - exu;
        float lam5 = 1.0f - (1.0f - SMEAR * u3) * exu;
        c3s[i * 129 + j] = __fdividef(lam3, r3raw + FEPS);
        c5s[i * 129 + j] = __fdividef(3.0f * lam5, R2 * r3raw + FEPS);
    }
    __syncthreads();

    int w = tid >> 5, lane = tid & 31;
    int gg = w & 7;
    int slice = w >> 3;
    int rrow = gg * 32 + lane;
    int mol = rrow >> 7;
    int n = rrow & 127;
    float4 cs = mol ? cpB[n] : cpA[n];
    const float4* cop = mol ? cpA : cpB;
    int c0 = slice * 32;

    {
        float sk = 0, sx = 0, sy = 0, sz = 0;
        #pragma unroll 4
        for (int c = 0; c < 32; c++) {
            int oth = c0 + c;
            float c3 = mol ? c3s[oth * 129 + n] : c3s[n * 129 + oth];
            float4 co = cop[oth];
            float wq = co.w * c3;
            sk += wq;
            sx = fmaf(wq, co.x, sx);
            sy = fmaf(wq, co.y, sy);
            sz = fmaf(wq, co.z, sz);
        }
        part[slice * 256 + rrow] = make_float4(fmaf(cs.x, sk, -sx),
                                               fmaf(cs.y, sk, -sy),
                                               fmaf(cs.z, sk, -sz), 0.0f);
    }
    __syncthreads();
    if (tid < 256) {
        float4 a0 = part[tid], a1 = part[256 + tid], a2 = part[512 + tid], a3 = part[768 + tid];
        float ex0 = a0.x + a1.x + a2.x + a3.x;
        float ey0 = a0.y + a1.y + a2.y + a3.y;
        float ez0 = a0.z + a1.z + a2.z + a3.z;
        int m = tid >> 7, nn = tid & 127;
        float4* e0p = m ? e0B : e0A;
        float pol = e0p[nn].w;
        e0p[nn] = make_float4(ex0, ey0, ez0, pol);
        float mux = pol * ex0, muy = pol * ey0, muz = pol * ez0;
        float4 cc = m ? cpB[nn] : cpA[nn];
        float dcm = cc.x * mux + cc.y * muy + cc.z * muz;
        (m ? muB : muA)[nn] = make_float4(mux, muy, muz, dcm);
    }
    __syncthreads();

    const float4* mop = mol ? muA : muB;
    for (int it = 0; it < 8; it++) {
        float sk = 0, sx = 0, sy = 0, sz = 0, tx = 0, ty = 0, tz = 0;
        #pragma unroll 4
        for (int c = 0; c < 32; c++) {
            int oth = c0 + c;
            float c3, c5;
            if (mol) { c3 = c3s[oth * 129 + n]; c5 = c5s[oth * 129 + n]; }
            else     { c3 = c3s[n * 129 + oth]; c5 = c5s[n * 129 + oth]; }
            float4 mo = mop[oth];
            float4 co = cop[oth];
            float rm = fmaf(cs.x, mo.x, fmaf(cs.y, mo.y, fmaf(cs.z, mo.z, -mo.w)));
            float k5 = c5 * rm;
            sk += k5;
            sx = fmaf(k5, co.x, sx);
            sy = fmaf(k5, co.y, sy);
            sz = fmaf(k5, co.z, sz);
            tx = fmaf(c3, mo.x, tx);
            ty = fmaf(c3, mo.y, ty);
            tz = fmaf(c3, mo.z, tz);
        }
        part[slice * 256 + rrow] = make_float4(fmaf(cs.x, sk, -sx) - tx,
                                               fmaf(cs.y, sk, -sy) - ty,
                                               fmaf(cs.z, sk, -sz) - tz, 0.0f);
        __syncthreads();
        if (tid < 256) {
            float4 a0 = part[tid], a1 = part[256 + tid], a2 = part[512 + tid], a3 = part[768 + tid];
            float ax = a0.x + a1.x + a2.x + a3.x;
            float ay = a0.y + a1.y + a2.y + a3.y;
            float az = a0.z + a1.z + a2.z + a3.z;
            int m = tid >> 7, nn = tid & 127;
            float4 e0 = (m ? e0B : e0A)[nn];
            float4 mo = (m ? muB : muA)[nn];
            float pol = e0.w;
            float fx = e0.x + ax, fy = e0.y + ay, fz = e0.z + az;
            float mux = fmaf(0.75f * pol, fx, 0.25f * mo.x);
            float muy = fmaf(0.75f * pol, fy, 0.25f * mo.y);
            float muz = fmaf(0.75f * pol, fz, 0.25f * mo.z);
            float4 cc = m ? cpB[nn] : cpA[nn];
            float dcm = cc.x * mux + cc.y * muy + cc.z * muz;
            (m ? muB : muA)[nn] = make_float4(mux, muy, muz, dcm);
        }
        __syncthreads();
    }

    float es_a = 0, ex_a = 0, dsp_a = 0, ct_a = 0;
    #pragma unroll 4
    for (int k = 0; k < 16; k++) {
        int p = tid + 1024 * k;
        int i = p >> 7, j = p & 127;
        float R = dist[b * NP + p];
        float C6  = g_pp[0][p], C8  = g_pp[1][p], C10 = g_pp[2][p];
        float r3  = g_pp[3][p], r4  = g_pp[4][p], r5  = g_pp[5][p];
        float Act = g_pp[6][p], bct = g_pp[7][p];
        float bd  = g_pp[8][p], be  = g_pp[9][p], Kp = g_pp[10][p];
        float4 c1p = cpA[i];
        float4 c2p = cpB[j];
        float4 m1 = muA[i];
        float4 m2 = muB[j];
        float B0 = __fdividef(1.0f, R + FEPS);
        float ebd = expf(-bd * R);
        es_a += c1p.w * c2p.w * (1.0f - fmaf(0.5f * bd, R, 1.0f) * ebd) * B0;
        ct_a += Act * expf(-bct * R);
        float R2 = R * R;
        if (R2 < 2500.0f) {
            float R6 = R2 * R2 * R2;
            float R8 = R6 * R2;
            float R10 = R8 * R2;
            dsp_a -= __fdividef(C6, R6 + r3) + __fdividef(C8, R8 + r4) + __fdividef(C10, R10 + r5);
        }
        float rhx = (c2p.x - c1p.x) * B0;
        float rhy = (c2p.y - c1p.y) * B0;
        float rhz = (c2p.z - c1p.z) * B0;
        float proj = (m1.x - m2.x) * rhx + (m1.y - m2.y) * rhy + (m1.z - m2.z) * rhz;
        ex_a += Kp * qeS[i] * qeS[128 + j] * (1.0f + proj) * expf(-be * R) * B0;
    }
    float iev = 0.0f;
    if (tid < 256) {
        int m = tid >> 7, nn = tid & 127;
        float4 mo = (m ? muB : muA)[nn];
        float4 e0 = (m ? e0B : e0A)[nn];
        iev = mo.x * e0.x + mo.y * e0.y + mo.z * e0.z;
    }
    __syncthreads();
    part[tid] = make_float4(es_a, ex_a, dsp_a, ct_a);
    ired[tid] = iev;
    __syncthreads();
    for (int s = 512; s; s >>= 1) {
        if (tid < s) {
            float4 a = part[tid], c = part[tid + s];
            part[tid] = make_float4(a.x + c.x, a.y + c.y, a.z + c.z, a.w + c.w);
            ired[tid] += ired[tid + s];
        }
        __syncthreads();
    }
    if (tid == 0) {
        float4 a = part[0];
        float in_t = -0.5f * ired[0] - a.w;
        out[b]        = a.y + a.z + a.x + in_t;
        out[64 + b]   = a.x;
        out[128 + b]  = in_t;
        out[192 + b]  = a.y;
        out[256 + b]  = a.z;
    }
}

// ---------------- launch ----------------
extern "C" void kernel_launch(void* const* d_in, const int* in_sizes, int n_in,
                              void* d_out, int out_size) {
    const float* nodes1    = (const float*)d_in[0];
    const float* edges1    = (const float*)d_in[1];
    const int*   senders1  = (const int*)d_in[2];
    const int*   receivers1= (const int*)d_in[3];
    const float* nodes2    = (const float*)d_in[4];
    const float* edges2    = (const float*)d_in[5];
    const int*   senders2  = (const int*)d_in[6];
    const int*   receivers2= (const int*)d_in[7];
    const float* coords1   = (const float*)d_in[8];
    const float* coords2   = (const float*)d_in[9];
    const float* dist;
    const float* mp;
    if (in_sizes[10] == 2 * BB * NN) {        // multipoles came first
        mp   = (const float*)d_in[10];
        dist = (const float*)d_in[11];
    } else {                                  // distance_matrices first (setup order)
        dist = (const float*)d_in[10];
        mp   = (const float*)d_in[11];
    }
    const float* W_emb_node = (const float*)d_in[12];
    const float* b_emb_node = (const float*)d_in[13];
    const float* W_emb_edge = (const float*)d_in[14];
    const float* b_emb_edge = (const float*)d_in[15];
    const float* W_gn_edge  = (const float*)d_in[16];
    const float* b_gn_edge  = (const float*)d_in[17];
    const float* W_gn_node  = (const float*)d_in[18];
    const float* b_gn_node  = (const float*)d_in[19];
    const float* pp_W0 = (const float*)d_in[20];
    const float* pp_b0 = (const float*)d_in[21];
    const float* pp_W1 = (const float*)d_in[22];
    const float* pp_b1 = (const float*)d_in[23];
    const float* pp_W2 = (const float*)d_in[24];
    const float* pp_b2 = (const float*)d_in[25];
    const float* ap_W0 = (const float*)d_in[26];
    const float* ap_b0 = (const float*)d_in[27];
    const float* ap_W1 = (const float*)d_in[28];
    const float* ap_b1 = (const float*)d_in[29];
    const float* ap_W2 = (const float*)d_in[30];
    const float* ap_b2 = (const float*)d_in[31];
    float* out = (float*)d_out;

    static int smem_set = 0;
    if (!smem_set) {
        cudaFuncSetAttribute(k_induct, cudaFuncAttributeMaxDynamicSharedMemorySize,
                             IND_SMEM_FLOATS * 4);
        smem_set = 1;
    }

    k_gnn<<<NBLK, 256>>>(nodes1, nodes2, edges1, edges2,
                         senders1, receivers1, senders2, receivers2,
                         W_emb_node, b_emb_node, W_emb_edge, b_emb_edge,
                         W_gn_edge, b_gn_edge, W_gn_node, b_gn_node,
                         ap_W0, ap_b0, ap_W1, ap_b1, ap_W2, ap_b2,
                         pp_W0, pp_b0, pp_W1, pp_b1, pp_W2, pp_b2,
                         mp, coords1, coords2);
    k_induct<<<BB, 1024, IND_SMEM_FLOATS * 4>>>(dist, out);
}

// round 15
// speedup vs baseline: 1.3214x; 1.0025x over previous
#include <cuda_runtime.h>
#include <math.h>

#define NN   128
#define NE   512
#define HID  64
#define BB   64
#define NP   16384     // NN*NN
#define SMEAR (-0.39f)
#define FEPS  1e-6f
#define NBLK 128       // persistent grid: <= SM count, all resident

// ---------------- device scratch (no allocation allowed) ----------------
__device__ float  g_n[2][2][NN][HID];     // [pingpong][mol][node][feat]
__device__ float  g_e[2][2][NE][HID];     // [pingpong][mol][edge][feat]
__device__ int    g_h[2][NN];
__device__ int    g_cnt[2][NN];
__device__ short  g_elist[2][NN][NE];
__device__ float  g_ap[2][NN][5];         // a_d, pol, K, dq, a_e
__device__ float  g_u[2][NN][HID];        // feats @ ppW0[0:64]
__device__ float  g_v[2][NN][HID];        // feats @ ppW0[64:128]
__device__ float  g_pp[11][NP];           // C6,C8,C10,r3,r4,r5,Act,bct,bd,be,Kp
__device__ float4 g_cpack[2][BB][NN];     // (cx,cy,cz,q)
__device__ float  g_qe[2][BB][NN];
__device__ float4 g_mu[2][BB][NN];        // dipoles (x,y,z, coord.mu)
__device__ float  g_fin[BB][2][5];        // per-CTA energy partials
__device__ int    g_pb[BB][24];           // pair barriers (memset each launch)
__device__ int           g_bar_count;     // self-resetting
__device__ volatile int  g_bar_gen;       // monotonic generation

// mila(x) = x * tanh(softplus(x-1)) = x * (1 - 2/((1+e^{x-1})^2 + 1))  (exact)
__device__ __forceinline__ float milaf(float x) {
    float t = expf(x - 1.0f);
    float a = 1.0f + t;
    float d = fmaf(a, a, 1.0f);
    return x * (1.0f - __fdividef(2.0f, d));
}
__device__ __forceinline__ float sspf(float x) {
    return fmaxf(x, 0.0f) + log1pf(expf(-fabsf(x))) + 0.001f;
}
__device__ __forceinline__ float wred(float v) {
    #pragma unroll
    for (int o = 16; o; o >>= 1) v += __shfl_xor_sync(0xffffffffu, v, o);
    return v;
}

// grid barrier: release fence per thread; acquire-side IVALL from tid0 only.
__device__ __forceinline__ void gridbar() {
    __threadfence();
    __syncthreads();
    if (threadIdx.x == 0) {
        int gen = g_bar_gen;
        if (atomicAdd(&g_bar_count, 1) == NBLK - 1) {
            g_bar_count = 0;
            __threadfence();
            g_bar_gen = gen + 1;
        } else {
            while (g_bar_gen == gen) __nanosleep(64);
        }
        __threadfence();          // per-SM L1 invalidate for fresh reads
    }
    __syncthreads();
}

// 2-CTA pair barrier on counter g_pb[b][k] (zeroed each launch). tid0 only.
__device__ __forceinline__ void pairbar(int b, int k) {
    atomicAdd(&g_pb[b][k], 1);
    while (atomicAdd(&g_pb[b][k], 0) < 2) __nanosleep(32);
}

// ================= persistent GNN + pair mega-kernel =================
__global__ void __launch_bounds__(256) k_gnn(
        const float* __restrict__ nodes1, const float* __restrict__ nodes2,
        const float* __restrict__ edges1, const float* __restrict__ edges2,
        const int* __restrict__ snd1, const int* __restrict__ rcv1,
        const int* __restrict__ snd2, const int* __restrict__ rcv2,
        const float* __restrict__ Wn, const float* __restrict__ bn,
        const float* __restrict__ We, const float* __restrict__ be_,
        const float* __restrict__ Wge, const float* __restrict__ bge,
        const float* __restrict__ Wgn, const float* __restrict__ bgn,
        const float* __restrict__ apW0, const float* __restrict__ apb0,
        const float* __restrict__ apW1, const float* __restrict__ apb1,
        const float* __restrict__ apW2, const float* __restrict__ apb2,
        const float* __restrict__ ppW0, const float* __restrict__ ppb0,
        const float* __restrict__ ppW1, const float* __restrict__ ppb1,
        const float* __restrict__ ppW2, const float* __restrict__ ppb2,
        const float* __restrict__ mp,
        const float* __restrict__ coords1, const float* __restrict__ coords2) {
    __shared__ float sbuf[12288];            // 48KB, reused across phases
    int tid = threadIdx.x;
    int bid = blockIdx.x;

    // ---------- P0: embed (127 blocks) + CSR build (block 127) ----------
    if (bid == NBLK - 1) {
        int m = tid >> 7, node = tid & 127;
        const int* rcv = m ? rcv2 : rcv1;
        int c = 0;
        for (int e = 0; e < NE; e++) {
            if (rcv[e] == node) g_elist[m][node][c++] = (short)e;
        }
        g_cnt[m][node] = c;
    } else {
        for (int g = bid * 256 + tid; g < 2 * NN * HID + 2 * NE * HID + 2 * NN;
             g += (NBLK - 1) * 256) {
            if (g < 2 * NN * HID) {
                int m = g / (NN * HID);
                int r = g % (NN * HID);
                int i = r / HID, o = r % HID;
                const float* nd = m ? nodes2 : nodes1;
                float acc = bn[o];
                #pragma unroll
                for (int k = 0; k < 16; k++)
                    acc = fmaf(nd[i * 16 + k], __ldg(Wn + k * HID + o), acc);
                g_n[0][m][i][o] = milaf(acc);
            } else if (g < 2 * NN * HID + 2 * NE * HID) {
                int r = g - 2 * NN * HID;
                int m = r / (NE * HID);
                r %= NE * HID;
                int ei = r / HID, o = r % HID;
                const float* ed = m ? edges2 : edges1;
                float acc = be_[o];
                #pragma unroll
                for (int k = 0; k < 8; k++)
                    acc = fmaf(ed[ei * 8 + k], __ldg(We + k * HID + o), acc);
                g_e[0][m][ei][o] = milaf(acc);
            } else {
                int r = g - (2 * NN * HID + 2 * NE * HID);
                int m = r >> 7, i = r & 127;
                const float* nd = m ? nodes2 : nodes1;
                float v0 = nd[i * 16];
                float mx = -1e30f;
                #pragma unroll
                for (int k = 1; k < 16; k++) mx = fmaxf(mx, nd[i * 16 + k]);
                g_h[m][i] = (v0 >= mx) ? 1 : 0;
            }
        }
    }
    gridbar();

    // ---------- message-passing steps ----------
    int ib = 0;
    for (int s = 0; s < 3; s++) {
        int ob = 1 - ib;

        // ----- edge phase: all 128 blocks, 2 chunks of 256 each -----
        {
            float* sW = sbuf;                  // 192*64 floats
            const float4* Wv = (const float4*)(Wge + s * 192 * 64);
            #pragma unroll
            for (int k = 0; k < 12; k++)
                ((float4*)sW)[tid + 256 * k] = Wv[tid + 256 * k];
            __syncthreads();
            #pragma unroll
            for (int ch = 0; ch < 2; ch++) {
                int g = bid * 256 + tid + ch * 32768;   // < 65536
                int m = g >> 15;
                int r = g & 32767;
                int e = r >> 6, o = r & 63;
                const int* snd = m ? snd2 : snd1;
                const int* rcv = m ? rcv2 : rcv1;
                int sidx = snd[e], ridx = rcv[e];
                const float4* er = (const float4*)&g_e[ib][m][e][0];
                const float4* nr = (const float4*)&g_n[ib][m][ridx][0];
                const float4* ns = (const float4*)&g_n[ib][m][sidx][0];
                float acc1 = bge[s * 64 + o];
                float acc2 = 0.0f;
                float acc3 = 0.0f;
                #pragma unroll 4
                for (int c = 0; c < 16; c++) {
                    float4 ev = er[c], rv = nr[c], sv = ns[c];
                    int k4 = 4 * c;
                    acc1 = fmaf(ev.x, sW[(k4 + 0) * 64 + o], acc1);
                    acc2 = fmaf(rv.x, sW[(64 + k4 + 0) * 64 + o], acc2);
                    acc3 = fmaf(sv.x, sW[(128 + k4 + 0) * 64 + o], acc3);
                    acc1 = fmaf(ev.y, sW[(k4 + 1) * 64 + o], acc1);
                    acc2 = fmaf(rv.y, sW[(64 + k4 + 1) * 64 + o], acc2);
                    acc3 = fmaf(sv.y, sW[(128 + k4 + 1) * 64 + o], acc3);
                    acc1 = fmaf(ev.z, sW[(k4 + 2) * 64 + o], acc1);
                    acc2 = fmaf(rv.z, sW[(64 + k4 + 2) * 64 + o], acc2);
                    acc3 = fmaf(sv.z, sW[(128 + k4 + 2) * 64 + o], acc3);
                    acc1 = fmaf(ev.w, sW[(k4 + 3) * 64 + o], acc1);
                    acc2 = fmaf(rv.w, sW[(64 + k4 + 3) * 64 + o], acc2);
                    acc3 = fmaf(sv.w, sW[(128 + k4 + 3) * 64 + o], acc3);
                }
                g_e[ob][m][e][o] = milaf(acc1 + acc2 + acc3);
            }
        }
        gridbar();

        // ----- node phase: blocks 0..63 (4 nodes per block) -----
        if (bid < 64) {
            float* sW   = sbuf;                // 128*64 floats
            float* sagg = sbuf + 8192;         // 256
            float* sf   = sbuf + 8448;         // 256
            float* sh1  = sbuf + 8704;         // 256
            float* sh2  = sbuf + 8960;         // 256
            int g = bid * 256 + tid;           // < 16384
            int m = g >> 13;
            int r = g & 8191;
            int i = r >> 6, o = r & 63;
            int nl = tid >> 6;
            int cnt = g_cnt[m][i];
            float agg = 0.0f;
            for (int c = 0; c < cnt; c++) agg += g_e[ob][m][g_elist[m][i][c]][o];
            const float4* Wv = (const float4*)(Wgn + s * 128 * 64);
            #pragma unroll
            for (int k = 0; k < 8; k++)
                ((float4*)sW)[tid + 256 * k] = Wv[tid + 256 * k];
            sagg[tid] = agg;
            __syncthreads();
            const float4* nr = (const float4*)&g_n[ib][m][i][0];
            const float4* ar = (const float4*)&sagg[nl * 64];
            float acc1 = bgn[s * 64 + o];
            float acc2 = 0.0f;
            #pragma unroll 4
            for (int c = 0; c < 16; c++) {
                float4 nv = nr[c], av = ar[c];
                int k4 = 4 * c;
                acc1 = fmaf(nv.x, sW[(k4 + 0) * 64 + o], acc1);
                acc2 = fmaf(av.x, sW[(64 + k4 + 0) * 64 + o], acc2);
                acc1 = fmaf(nv.y, sW[(k4 + 1) * 64 + o], acc1);
                acc2 = fmaf(av.y, sW[(64 + k4 + 1) * 64 + o], acc2);
                acc1 = fmaf(nv.z, sW[(k4 + 2) * 64 + o], acc1);
                acc2 = fmaf(av.z, sW[(64 + k4 + 2) * 64 + o], acc2);
                acc1 = fmaf(nv.w, sW[(k4 + 3) * 64 + o], acc1);
                acc2 = fmaf(av.w, sW[(64 + k4 + 3) * 64 + o], acc2);
            }
            float val = milaf(acc1 + acc2);
            g_n[ob][m][i][o] = val;
            if (s == 2) {   // fused post: atom props + pair-layer-0 factorization
                sf[tid] = val;
                __syncthreads();
                const float* f = &sf[nl * 64];
                float a = apb0[o], su = 0.0f, sv = 0.0f;
                #pragma unroll 8
                for (int k = 0; k < 64; k++) {
                    float fk = f[k];
                    a  = fmaf(fk, __ldg(apW0 + k * 64 + o), a);
                    su = fmaf(fk, __ldg(ppW0 + k * 64 + o), su);
                    sv = fmaf(fk, __ldg(ppW0 + (64 + k) * 64 + o), sv);
                }
                sh1[tid] = milaf(a);
                g_u[m][i][o] = su;
                g_v[m][i][o] = sv;
                __syncthreads();
                float a1 = apb1[o];
                const float* h1 = &sh1[nl * 64];
                #pragma unroll 8
                for (int k = 0; k < 64; k++)
                    a1 = fmaf(h1[k], __ldg(apW1 + k * 64 + o), a1);
                sh2[tid] = milaf(a1);
                __syncthreads();
                if (o < 5) {
                    float a2 = apb2[o];
                    const float* h2 = &sh2[nl * 64];
                    for (int k = 0; k < 64; k++)
                        a2 = fmaf(h2[k], __ldg(apW2 + k * 5 + o), a2);
                    g_ap[m][i][o] = sspf(a2);
                }
            }
        }
        gridbar();
        ib = ob;
    }

    // ---------- pair phase: all 128 blocks, 128 pairs each ----------
    {
        int idx = bid * 256 + tid;
        if (idx < 2 * BB * NN) {
            int m = idx >> 13;
            int r = idx & 8191;
            int b = r >> 7, n = r & 127;
            float q = mp[(m * BB + b) * NN + n];
            float dq = g_ap[m][n][3];
            float qe = g_h[m][n] ? (1.0f - q) : (2.0f + dq - q);
            g_qe[m][b][n] = qe;
            const float* cc = (m ? coords2 : coords1) + (b * NN + n) * 3;
            g_cpack[m][b][n] = make_float4(cc[0], cc[1], cc[2], q);
        }
        float* sW1 = sbuf;            // 4096
        float* sW2 = sbuf + 4096;     // 320
        float* sb0 = sbuf + 4416;     // 64
        float* sb1 = sbuf + 4480;     // 64
        float* sb2 = sbuf + 4544;     // 8
        float* shh = sbuf + 4608;     // 8*64
        for (int k = tid; k < 4096; k += 256) sW1[k] = ppW1[k];
        for (int k = tid; k < 320; k += 256) sW2[k] = ppW2[k];
        if (tid < 64) { sb0[tid] = ppb0[tid]; sb1[tid] = ppb1[tid]; }
        if (tid < 5)  sb2[tid] = ppb2[tid];
        __syncthreads();
        int warp = tid >> 5, lane = tid & 31;
        float* hw = shh + warp * 64;
        for (int t = 0; t < 16; t++) {
            int p = bid * 128 + warp * 16 + t;      // < 16384
            int i = p >> 7, j = p & 127;
            float pr0 = 0, pr1 = 0, pr2 = 0, pr3 = 0, pr4 = 0;
            #pragma unroll
            for (int d = 0; d < 2; d++) {
                const float* U = d ? g_u[1][j] : g_u[0][i];
                const float* V = d ? g_v[0][i] : g_v[1][j];
                float2 uu = *(const float2*)(U + 2 * lane);
                float2 vv = *(const float2*)(V + 2 * lane);
                float h0 = milaf(uu.x + vv.x + sb0[2 * lane]);
                float h1 = milaf(uu.y + vv.y + sb0[2 * lane + 1]);
                __syncwarp();
                hw[2 * lane] = h0; hw[2 * lane + 1] = h1;
                __syncwarp();
                float a0 = sb1[2 * lane], a1 = sb1[2 * lane + 1];
                #pragma unroll 8
                for (int k = 0; k < 64; k++) {
                    float hk = hw[k];
                    float2 w = *(const float2*)(sW1 + k * 64 + 2 * lane);
                    a0 = fmaf(hk, w.x, a0);
                    a1 = fmaf(hk, w.y, a1);
                }
                float g0 = milaf(a0), g1 = milaf(a1);
                const float* w2a = sW2 + (2 * lane) * 5;
                const float* w2b = sW2 + (2 * lane + 1) * 5;
                float p0 = g0 * w2a[0] + g1 * w2b[0];
                float p1 = g0 * w2a[1] + g1 * w2b[1];
                float p2 = g0 * w2a[2] + g1 * w2b[2];
                float p3 = g0 * w2a[3] + g1 * w2b[3];
                float p4 = g0 * w2a[4] + g1 * w2b[4];
                p0 = wred(p0); p1 = wred(p1); p2 = wred(p2); p3 = wred(p3); p4 = wred(p4);
                pr0 += sspf(p0 + sb2[0]);
                pr1 += sspf(p1 + sb2[1]);
                pr2 += sspf(p2 + sb2[2]);
                pr3 += sspf(p3 + sb2[3]);
                pr4 += sspf(p4 + sb2[4]);
            }
            if (lane == 0) {
                float C6 = pr0, C8 = pr1, C10 = pr2, Act = pr3, bct = pr4;
                float r02 = C8 / (C6 + FEPS);
                float r3 = r02 * r02 * r02, r4 = r3 * r02, r5 = r4 * r02;
                float bd = sqrtf(g_ap[0][i][0] * g_ap[1][j][0]);
                float be = sqrtf(g_ap[0][i][4] * g_ap[1][j][4]);
                float Kp = g_ap[0][i][2] * g_ap[1][j][2];
                g_pp[0][p] = C6;  g_pp[1][p] = C8;  g_pp[2][p] = C10;
                g_pp[3][p] = r3;  g_pp[4][p] = r4;  g_pp[5][p] = r5;
                g_pp[6][p] = Act; g_pp[7][p] = bct; g_pp[8][p] = bd;
                g_pp[9][p] = be;  g_pp[10][p] = Kp;
            }
        }
    }
}

// ======= induction + energy: TWO CTAs per batch (one per molecule) =======
// smem floats: c3s+c5s 2*128*129=33024, cpO/cpX/muO/muX/e0O 5*512=2560, part 4096
#define IND2_SMEM_FLOATS (33024 + 2560 + 4096)

__global__ void __launch_bounds__(1024, 1) k_induct(const float* __restrict__ dist,
                                                    float* __restrict__ out) {
    extern __shared__ float smem[];
    float*  c3s = smem;                       // [row:own atom][col:other atom], 129 pitch
    float*  c5s = smem + 16512;
    float4* cpO = (float4*)(smem + 33024);    // own cpack
    float4* cpX = cpO + 128;                  // other cpack
    float4* muO = cpX + 128;                  // own mu (x,y,z, c.mu)
    float4* muX = muO + 128;                  // staged peer mu
    float4* e0O = muX + 128;                  // own E0 (+pol in w)
    float4* part = (float4*)(e0O + 128);      // [8][128] slice partials / 1024 red
    float*  ired = c3s;                       // reuse after iterations

    int bid = blockIdx.x;
    int b = bid >> 1, half = bid & 1;         // half = molecule this CTA owns
    int tid = threadIdx.x;                    // 1024 threads
    int nb = 0;

    if (tid < 128) {
        cpO[tid] = g_cpack[half][b][tid];
        cpX[tid] = g_cpack[1 - half][b][tid];
        float pol = g_ap[half][tid][1];
        e0O[tid] = make_float4(0.0f, 0.0f, 0.0f, pol);
    }
    __syncthreads();

    // ---- c3/c5 in own orientation (coalesced dist read; transposed STS ok) ----
    #pragma unroll
    for (int k = 0; k < 16; k++) {
        int p = tid + 1024 * k;
        int iA = p >> 7, jB = p & 127;
        float R = dist[b * NP + p];
        float polA = __ldg(&g_ap[0][iA][1]);
        float polB = __ldg(&g_ap[1][jB][1]);
        float au = sqrtf(polA * polB) + FEPS;
        float R2 = R * R;
        float r3raw = R2 * R;
        float u3 = __fdividef(r3raw, au);
        float exu = expf(SMEAR * u3);
        float lam3 = 1.0f - exu;
        float lam5 = 1.0f - (1.0f - SMEAR * u3) * exu;
        float c3v = __fdividef(lam3, r3raw + FEPS);
        float c5v = __fdividef(3.0f * lam5, R2 * r3raw + FEPS);
        int row = half ? jB : iA;
        int col = half ? iA : jB;
        c3s[row * 129 + col] = c3v;
        c5s[row * 129 + col] = c5v;
    }
    __syncthreads();

    // ---- warp map: 4 row-groups x 8 col-slices of 16 ----
    int w = tid >> 5, lane = tid & 31;
    int rg = w & 3;
    int slice = w >> 2;
    int row = rg * 32 + lane;                 // own atom 0..127
    int c0 = slice * 16;
    float4 cs = cpO[row];

    // ---- E0: E0_row = cs*sum(q c3) - sum(q c3 co) ----
    {
        float sk = 0, sx = 0, sy = 0, sz = 0;
        #pragma unroll 4
        for (int c = 0; c < 16; c++) {
            int oth = c0 + c;
            float c3 = c3s[row * 129 + oth];
            float4 co = cpX[oth];
            float wq = co.w * c3;
            sk += wq;
            sx = fmaf(wq, co.x, sx);
            sy = fmaf(wq, co.y, sy);
            sz = fmaf(wq, co.z, sz);
        }
        part[slice * 128 + row] = make_float4(fmaf(cs.x, sk, -sx),
                                              fmaf(cs.y, sk, -sy),
                                              fmaf(cs.z, sk, -sz), 0.0f);
    }
    __syncthreads();
    if (tid < 128) {
        float ex0 = 0, ey0 = 0, ez0 = 0;
        #pragma unroll
        for (int sl = 0; sl < 8; sl++) {
            float4 a = part[sl * 128 + tid];
            ex0 += a.x; ey0 += a.y; ez0 += a.z;
        }
        float pol = e0O[tid].w;
        e0O[tid] = make_float4(ex0, ey0, ez0, pol);
        float4 cc = cpO[tid];
        float mux = pol * ex0, muy = pol * ey0, muz = pol * ez0;
        float dcm = cc.x * mux + cc.y * muy + cc.z * muz;
        float4 mv = make_float4(mux, muy, muz, dcm);
        muO[tid] = mv;
        g_mu[half][b][tid] = mv;
        __threadfence();
    }
    __syncthreads();
    if (tid == 0) pairbar(b, nb);
    __syncthreads();
    nb++;
    if (tid < 128) muX[tid] = __ldcg(&g_mu[1 - half][b][tid]);
    __syncthreads();
    if (tid == 0) pairbar(b, nb);
    __syncthreads();
    nb++;

    // ---- 8 fixed-point iterations ----
    for (int it = 0; it < 8; it++) {
        float sk = 0, sx = 0, sy = 0, sz = 0, tx = 0, ty = 0, tz = 0;
        #pragma unroll 4
        for (int c = 0; c < 16; c++) {
            int oth = c0 + c;
            float c3 = c3s[row * 129 + oth];
            float c5 = c5s[row * 129 + oth];
            float4 mo = muX[oth];
            float4 co = cpX[oth];
            float rm = fmaf(cs.x, mo.x, fmaf(cs.y, mo.y, fmaf(cs.z, mo.z, -mo.w)));
            float k5 = c5 * rm;
            sk += k5;
            sx = fmaf(k5, co.x, sx);
            sy = fmaf(k5, co.y, sy);
            sz = fmaf(k5, co.z, sz);
            tx = fmaf(c3, mo.x, tx);
            ty = fmaf(c3, mo.y, ty);
            tz = fmaf(c3, mo.z, tz);
        }
        part[slice * 128 + row] = make_float4(fmaf(cs.x, sk, -sx) - tx,
                                              fmaf(cs.y, sk, -sy) - ty,
                                              fmaf(cs.z, sk, -sz) - tz, 0.0f);
        __syncthreads();
        if (tid < 128) {
            float ax = 0, ay = 0, az = 0;
            #pragma unroll
            for (int sl = 0; sl < 8; sl++) {
                float4 a = part[sl * 128 + tid];
                ax += a.x; ay += a.y; az += a.z;
            }
            float4 e0 = e0O[tid];
            float4 mo = muO[tid];
            float pol = e0.w;
            float fx = e0.x + ax, fy = e0.y + ay, fz = e0.z + az;
            float mux = fmaf(0.75f * pol, fx, 0.25f * mo.x);
            float muy = fmaf(0.75f * pol, fy, 0.25f * mo.y);
            float muz = fmaf(0.75f * pol, fz, 0.25f * mo.z);
            float4 cc = cpO[tid];
            float dcm = cc.x * mux + cc.y * muy + cc.z * muz;
            float4 mv = make_float4(mux, muy, muz, dcm);
            muO[tid] = mv;
            g_mu[half][b][tid] = mv;
            __threadfence();
        }
        __syncthreads();
        if (tid == 0) pairbar(b, nb);
        __syncthreads();
        nb++;
        if (tid < 128) muX[tid] = __ldcg(&g_mu[1 - half][b][tid]);
        __syncthreads();
        if (tid == 0) pairbar(b, nb);
        __syncthreads();
        nb++;
    }

    // ---- energy: this CTA handles 8192 pairs ----
    const float4* muAp = half ? muX : muO;
    const float4* muBp = half ? muO : muX;
    const float4* cpAp = half ? cpX : cpO;
    const float4* cpBp = half ? cpO : cpX;
    float es_a = 0, ex_a = 0, dsp_a = 0, ct_a = 0;
    #pragma unroll 4
    for (int k = 0; k < 8; k++) {
        int p = half * 8192 + tid + 1024 * k;
        int i = p >> 7, j = p & 127;
        float R = dist[b * NP + p];
        float C6  = __ldg(&g_pp[0][p]), C8  = __ldg(&g_pp[1][p]), C10 = __ldg(&g_pp[2][p]);
        float r3  = __ldg(&g_pp[3][p]), r4  = __ldg(&g_pp[4][p]), r5  = __ldg(&g_pp[5][p]);
        float Act = __ldg(&g_pp[6][p]), bct = __ldg(&g_pp[7][p]);
        float bd  = __ldg(&g_pp[8][p]), be  = __ldg(&g_pp[9][p]), Kp = __ldg(&g_pp[10][p]);
        float4 c1p = cpAp[i];
        float4 c2p = cpBp[j];
        float4 m1 = muAp[i];
        float4 m2 = muBp[j];
        float B0 = __fdividef(1.0f, R + FEPS);
        float ebd = expf(-bd * R);
        es_a += c1p.w * c2p.w * (1.0f - fmaf(0.5f * bd, R, 1.0f) * ebd) * B0;
        ct_a += Act * expf(-bct * R);
        float R2 = R * R;
        if (R2 < 2500.0f) {
            float R6 = R2 * R2 * R2;
            float R8 = R6 * R2;
            float R10 = R8 * R2;
            dsp_a -= __fdividef(C6, R6 + r3) + __fdividef(C8, R8 + r4) + __fdividef(C10, R10 + r5);
        }
        float rhx = (c2p.x - c1p.x) * B0;
        float rhy = (c2p.y - c1p.y) * B0;
        float rhz = (c2p.z - c1p.z) * B0;
        float proj = (m1.x - m2.x) * rhx + (m1.y - m2.y) * rhy + (m1.z - m2.z) * rhz;
        float qe1 = __ldg(&g_qe[0][b][i]);
        float qe2 = __ldg(&g_qe[1][b][j]);
        ex_a += Kp * qe1 * qe2 * (1.0f + proj) * expf(-be * R) * B0;
    }
    float iev = 0.0f;
    if (tid < 128) {
        float4 mo = muO[tid];
        float4 e0 = e0O[tid];
        iev = mo.x * e0.x + mo.y * e0.y + mo.z * e0.z;
    }
    __syncthreads();
    part[tid] = make_float4(es_a, ex_a, dsp_a, ct_a);
    ired[tid] = iev;
    __syncthreads();
    for (int s = 512; s; s >>= 1) {
        if (tid < s) {
            float4 a = part[tid], c = part[tid + s];
            part[tid] = make_float4(a.x + c.x, a.y + c.y, a.z + c.z, a.w + c.w);
            ired[tid] += ired[tid + s];
        }
        __syncthreads();
    }
    if (tid == 0) {
        float4 a = part[0];
        g_fin[b][half][0] = a.x;
        g_fin[b][half][1] = a.y;
        g_fin[b][half][2] = a.z;
        g_fin[b][half][3] = a.w;
        g_fin[b][half][4] = ired[0];
        __threadfence();
        pairbar(b, nb);
        if (half == 0) {
            float es  = a.x + __ldcg(&g_fin[b][1][0]);
            float ex  = a.y + __ldcg(&g_fin[b][1][1]);
            float dsp = a.z + __ldcg(&g_fin[b][1][2]);
            float ct  = a.w + __ldcg(&g_fin[b][1][3]);
            float ie  = ired[0] + __ldcg(&g_fin[b][1][4]);
            float in_t = -0.5f * ie - ct;
            out[b]        = ex + dsp + es + in_t;
            out[64 + b]   = es;
            out[128 + b]  = in_t;
            out[192 + b]  = ex;
            out[256 + b]  = dsp;
        }
    }
}

// ---------------- launch ----------------
extern "C" void kernel_launch(void* const* d_in, const int* in_sizes, int n_in,
                              void* d_out, int out_size) {
    const float* nodes1    = (const float*)d_in[0];
    const float* edges1    = (const float*)d_in[1];
    const int*   senders1  = (const int*)d_in[2];
    const int*   receivers1= (const int*)d_in[3];
    const float* nodes2    = (const float*)d_in[4];
    const float* edges2    = (const float*)d_in[5];
    const int*   senders2  = (const int*)d_in[6];
    const int*   receivers2= (const int*)d_in[7];
    const float* coords1   = (const float*)d_in[8];
    const float* coords2   = (const float*)d_in[9];
    const float* dist;
    const float* mp;
    if (in_sizes[10] == 2 * BB * NN) {        // multipoles came first
        mp   = (const float*)d_in[10];
        dist = (const float*)d_in[11];
    } else {                                  // distance_matrices first (setup order)
        dist = (const float*)d_in[10];
        mp   = (const float*)d_in[11];
    }
    const float* W_emb_node = (const float*)d_in[12];
    const float* b_emb_node = (const float*)d_in[13];
    const float* W_emb_edge = (const float*)d_in[14];
    const float* b_emb_edge = (const float*)d_in[15];
    const float* W_gn_edge  = (const float*)d_in[16];
    const float* b_gn_edge  = (const float*)d_in[17];
    const float* W_gn_node  = (const float*)d_in[18];
    const float* b_gn_node  = (const float*)d_in[19];
    const float* pp_W0 = (const float*)d_in[20];
    const float* pp_b0 = (const float*)d_in[21];
    const float* pp_W1 = (const float*)d_in[22];
    const float* pp_b1 = (const float*)d_in[23];
    const float* pp_W2 = (const float*)d_in[24];
    const float* pp_b2 = (const float*)d_in[25];
    const float* ap_W0 = (const float*)d_in[26];
    const float* ap_b0 = (const float*)d_in[27];
    const float* ap_W1 = (const float*)d_in[28];
    const float* ap_b1 = (const float*)d_in[29];
    const float* ap_W2 = (const float*)d_in[30];
    const float* ap_b2 = (const float*)d_in[31];
    float* out = (float*)d_out;

    static int smem_set = 0;
    static void* pb_addr = nullptr;
    if (!smem_set) {
        cudaFuncSetAttribute(k_induct, cudaFuncAttributeMaxDynamicSharedMemorySize,
                             IND2_SMEM_FLOATS * 4);
        cudaGetSymbolAddress(&pb_addr, g_pb);
        smem_set = 1;
    }

    cudaMemsetAsync(pb_addr, 0, sizeof(int) * BB * 24);   // reset pair barriers
    k_gnn<<<NBLK, 256>>>(nodes1, nodes2, edges1, edges2,
                         senders1, receivers1, senders2, receivers2,
                         W_emb_node, b_emb_node, W_emb_edge, b_emb_edge,
                         W_gn_edge, b_gn_edge, W_gn_node, b_gn_node,
                         ap_W0, ap_b0, ap_W1, ap_b1, ap_W2, ap_b2,
                         pp_W0, pp_b0, pp_W1, pp_b1, pp_W2, pp_b2,
                         mp, coords1, coords2);
    k_induct<<<2 * BB, 1024, IND2_SMEM_FLOATS * 4>>>(dist, out);
}

// round 16
// speedup vs baseline: 1.6443x; 1.2444x over previous
#include <cuda_runtime.h>
#include <cooperative_groups.h>
#include <math.h>

namespace cg = cooperative_groups;

#define NN   128
#define NE   512
#define HID  64
#define BB   64
#define NP   16384     // NN*NN
#define SMEAR (-0.39f)
#define FEPS  1e-6f
#define NBLK 256       // persistent grid: 2 blocks/SM, all resident (capacity 296)

// ---------------- device scratch (no allocation allowed) ----------------
__device__ float  g_n[2][2][NN][HID];     // [pingpong][mol][node][feat]
__device__ float  g_e[2][2][NE][HID];     // [pingpong][mol][edge][feat]
__device__ int    g_h[2][NN];
__device__ int    g_cnt[2][NN];
__device__ short  g_elist[2][NN][NE];
__device__ float  g_ap[2][NN][5];         // a_d, pol, K, dq, a_e
__device__ float  g_u[2][NN][HID];        // feats @ ppW0[0:64]
__device__ float  g_v[2][NN][HID];        // feats @ ppW0[64:128]
__device__ float  g_pp[11][NP];           // C6,C8,C10,r3,r4,r5,Act,bct,bd,be,Kp
__device__ float4 g_cpack[2][BB][NN];     // (cx,cy,cz,q)
__device__ float  g_qe[2][BB][NN];
__device__ int           g_bar_count;     // self-resetting
__device__ volatile int  g_bar_gen;       // monotonic generation

// mila(x) = x * tanh(softplus(x-1)) = x * (1 - 2/((1+e^{x-1})^2 + 1))  (exact)
__device__ __forceinline__ float milaf(float x) {
    float t = expf(x - 1.0f);
    float a = 1.0f + t;
    float d = fmaf(a, a, 1.0f);
    return x * (1.0f - __fdividef(2.0f, d));
}
__device__ __forceinline__ float sspf(float x) {
    return fmaxf(x, 0.0f) + log1pf(expf(-fabsf(x))) + 0.001f;
}
__device__ __forceinline__ float wred(float v) {
    #pragma unroll
    for (int o = 16; o; o >>= 1) v += __shfl_xor_sync(0xffffffffu, v, o);
    return v;
}

// grid barrier: release fence per thread; acquire-side IVALL from tid0 only.
__device__ __forceinline__ void gridbar() {
    __threadfence();
    __syncthreads();
    if (threadIdx.x == 0) {
        int gen = g_bar_gen;
        if (atomicAdd(&g_bar_count, 1) == NBLK - 1) {
            g_bar_count = 0;
            __threadfence();
            g_bar_gen = gen + 1;
        } else {
            while (g_bar_gen == gen) __nanosleep(64);
        }
        __threadfence();          // per-SM L1 invalidate for fresh reads
    }
    __syncthreads();
}

// ================= persistent GNN + pair mega-kernel =================
__global__ void __launch_bounds__(256) k_gnn(
        const float* __restrict__ nodes1, const float* __restrict__ nodes2,
        const float* __restrict__ edges1, const float* __restrict__ edges2,
        const int* __restrict__ snd1, const int* __restrict__ rcv1,
        const int* __restrict__ snd2, const int* __restrict__ rcv2,
        const float* __restrict__ Wn, const float* __restrict__ bn,
        const float* __restrict__ We, const float* __restrict__ be_,
        const float* __restrict__ Wge, const float* __restrict__ bge,
        const float* __restrict__ Wgn, const float* __restrict__ bgn,
        const float* __restrict__ apW0, const float* __restrict__ apb0,
        const float* __restrict__ apW1, const float* __restrict__ apb1,
        const float* __restrict__ apW2, const float* __restrict__ apb2,
        const float* __restrict__ ppW0, const float* __restrict__ ppb0,
        const float* __restrict__ ppW1, const float* __restrict__ ppb1,
        const float* __restrict__ ppW2, const float* __restrict__ ppb2,
        const float* __restrict__ mp,
        const float* __restrict__ coords1, const float* __restrict__ coords2) {
    __shared__ float sbuf[12288];            // 48KB, reused across phases
    int tid = threadIdx.x;
    int bid = blockIdx.x;

    // ---------- P0: embed (255 blocks) + CSR build (block 255) ----------
    if (bid == NBLK - 1) {
        int m = tid >> 7, node = tid & 127;
        const int* rcv = m ? rcv2 : rcv1;
        int c = 0;
        for (int e = 0; e < NE; e++) {
            if (rcv[e] == node) g_elist[m][node][c++] = (short)e;
        }
        g_cnt[m][node] = c;
    } else {
        for (int g = bid * 256 + tid; g < 2 * NN * HID + 2 * NE * HID + 2 * NN;
             g += (NBLK - 1) * 256) {
            if (g < 2 * NN * HID) {
                int m = g / (NN * HID);
                int r = g % (NN * HID);
                int i = r / HID, o = r % HID;
                const float* nd = m ? nodes2 : nodes1;
                float acc = bn[o];
                #pragma unroll
                for (int k = 0; k < 16; k++)
                    acc = fmaf(nd[i * 16 + k], __ldg(Wn + k * HID + o), acc);
                g_n[0][m][i][o] = milaf(acc);
            } else if (g < 2 * NN * HID + 2 * NE * HID) {
                int r = g - 2 * NN * HID;
                int m = r / (NE * HID);
                r %= NE * HID;
                int ei = r / HID, o = r % HID;
                const float* ed = m ? edges2 : edges1;
                float acc = be_[o];
                #pragma unroll
                for (int k = 0; k < 8; k++)
                    acc = fmaf(ed[ei * 8 + k], __ldg(We + k * HID + o), acc);
                g_e[0][m][ei][o] = milaf(acc);
            } else {
                int r = g - (2 * NN * HID + 2 * NE * HID);
                int m = r >> 7, i = r & 127;
                const float* nd = m ? nodes2 : nodes1;
                float v0 = nd[i * 16];
                float mx = -1e30f;
                #pragma unroll
                for (int k = 1; k < 16; k++) mx = fmaxf(mx, nd[i * 16 + k]);
                g_h[m][i] = (v0 >= mx) ? 1 : 0;
            }
        }
    }
    gridbar();

    // ---------- message-passing steps ----------
    int ib = 0;
    for (int s = 0; s < 3; s++) {
        int ob = 1 - ib;

        // ----- edge phase: 256 blocks x 256 = 65536 items, one each -----
        {
            float* sW = sbuf;                  // 192*64 floats
            const float4* Wv = (const float4*)(Wge + s * 192 * 64);
            #pragma unroll
            for (int k = 0; k < 12; k++)
                ((float4*)sW)[tid + 256 * k] = Wv[tid + 256 * k];
            __syncthreads();
            int g = bid * 256 + tid;
            int m = g >> 15;
            int r = g & 32767;
            int e = r >> 6, o = r & 63;
            const int* snd = m ? snd2 : snd1;
            const int* rcv = m ? rcv2 : rcv1;
            int sidx = snd[e], ridx = rcv[e];
            const float4* er = (const float4*)&g_e[ib][m][e][0];
            const float4* nr = (const float4*)&g_n[ib][m][ridx][0];
            const float4* ns = (const float4*)&g_n[ib][m][sidx][0];
            float acc1 = bge[s * 64 + o];
            float acc2 = 0.0f;
            float acc3 = 0.0f;
            #pragma unroll 4
            for (int c = 0; c < 16; c++) {
                float4 ev = er[c], rv = nr[c], sv = ns[c];
                int k4 = 4 * c;
                acc1 = fmaf(ev.x, sW[(k4 + 0) * 64 + o], acc1);
                acc2 = fmaf(rv.x, sW[(64 + k4 + 0) * 64 + o], acc2);
                acc3 = fmaf(sv.x, sW[(128 + k4 + 0) * 64 + o], acc3);
                acc1 = fmaf(ev.y, sW[(k4 + 1) * 64 + o], acc1);
                acc2 = fmaf(rv.y, sW[(64 + k4 + 1) * 64 + o], acc2);
                acc3 = fmaf(sv.y, sW[(128 + k4 + 1) * 64 + o], acc3);
                acc1 = fmaf(ev.z, sW[(k4 + 2) * 64 + o], acc1);
                acc2 = fmaf(rv.z, sW[(64 + k4 + 2) * 64 + o], acc2);
                acc3 = fmaf(sv.z, sW[(128 + k4 + 2) * 64 + o], acc3);
                acc1 = fmaf(ev.w, sW[(k4 + 3) * 64 + o], acc1);
                acc2 = fmaf(rv.w, sW[(64 + k4 + 3) * 64 + o], acc2);
                acc3 = fmaf(sv.w, sW[(128 + k4 + 3) * 64 + o], acc3);
            }
            g_e[ob][m][e][o] = milaf(acc1 + acc2 + acc3);
        }
        gridbar();

        // ----- node phase: blocks 0..127, 2 nodes per block (128 active thr) -----
        if (bid < 128) {
            float* sW   = sbuf;                // 8192 floats
            float* sagg = sbuf + 8192;         // 128
            float* sf   = sbuf + 8320;         // 128
            float* sh1  = sbuf + 8448;         // 128
            float* sh2  = sbuf + 8576;         // 128
            // all 256 threads preload weights
            const float4* Wv = (const float4*)(Wgn + s * 128 * 64);
            #pragma unroll
            for (int k = 0; k < 8; k++)
                ((float4*)sW)[tid + 256 * k] = Wv[tid + 256 * k];
            int g = bid * 128 + tid;           // valid for tid<128
            int m = g >> 13;
            int i = (g >> 6) & 127;
            int o = g & 63;
            int nl = (tid >> 6) & 1;
            if (tid < 128) {
                int cnt = g_cnt[m][i];
                float agg = 0.0f;
                for (int c = 0; c < cnt; c++) agg += g_e[ob][m][g_elist[m][i][c]][o];
                sagg[tid] = agg;
            }
            __syncthreads();
            float val = 0.0f;
            if (tid < 128) {
                const float4* nr = (const float4*)&g_n[ib][m][i][0];
                const float4* ar = (const float4*)&sagg[nl * 64];
                float acc1 = bgn[s * 64 + o];
                float acc2 = 0.0f;
                #pragma unroll 4
                for (int c = 0; c < 16; c++) {
                    float4 nv = nr[c], av = ar[c];
                    int k4 = 4 * c;
                    acc1 = fmaf(nv.x, sW[(k4 + 0) * 64 + o], acc1);
                    acc2 = fmaf(av.x, sW[(64 + k4 + 0) * 64 + o], acc2);
                    acc1 = fmaf(nv.y, sW[(k4 + 1) * 64 + o], acc1);
                    acc2 = fmaf(av.y, sW[(64 + k4 + 1) * 64 + o], acc2);
                    acc1 = fmaf(nv.z, sW[(k4 + 2) * 64 + o], acc1);
                    acc2 = fmaf(av.z, sW[(64 + k4 + 2) * 64 + o], acc2);
                    acc1 = fmaf(nv.w, sW[(k4 + 3) * 64 + o], acc1);
                    acc2 = fmaf(av.w, sW[(64 + k4 + 3) * 64 + o], acc2);
                }
                val = milaf(acc1 + acc2);
                g_n[ob][m][i][o] = val;
            }
            if (s == 2) {   // fused post: atom props + pair-layer-0 factorization
                if (tid < 128) sf[tid] = val;
                __syncthreads();
                if (tid < 128) {
                    const float* f = &sf[nl * 64];
                    float a = apb0[o], su = 0.0f, sv = 0.0f;
                    #pragma unroll 8
                    for (int k = 0; k < 64; k++) {
                        float fk = f[k];
                        a  = fmaf(fk, __ldg(apW0 + k * 64 + o), a);
                        su = fmaf(fk, __ldg(ppW0 + k * 64 + o), su);
                        sv = fmaf(fk, __ldg(ppW0 + (64 + k) * 64 + o), sv);
                    }
                    sh1[tid] = milaf(a);
                    g_u[m][i][o] = su;
                    g_v[m][i][o] = sv;
                }
                __syncthreads();
                if (tid < 128) {
                    float a1 = apb1[o];
                    const float* h1 = &sh1[nl * 64];
                    #pragma unroll 8
                    for (int k = 0; k < 64; k++)
                        a1 = fmaf(h1[k], __ldg(apW1 + k * 64 + o), a1);
                    sh2[tid] = milaf(a1);
                }
                __syncthreads();
                if (tid < 128 && o < 5) {
                    float a2 = apb2[o];
                    const float* h2 = &sh2[nl * 64];
                    for (int k = 0; k < 64; k++)
                        a2 = fmaf(h2[k], __ldg(apW2 + k * 5 + o), a2);
                    g_ap[m][i][o] = sspf(a2);
                }
            }
        }
        gridbar();
        ib = ob;
    }

    // ---------- pair phase: 256 blocks x 64 pairs ----------
    {
        int idx = bid * 256 + tid;
        if (idx < 2 * BB * NN) {
            int m = idx >> 13;
            int r = idx & 8191;
            int b = r >> 7, n = r & 127;
            float q = mp[(m * BB + b) * NN + n];
            float dq = g_ap[m][n][3];
            float qe = g_h[m][n] ? (1.0f - q) : (2.0f + dq - q);
            g_qe[m][b][n] = qe;
            const float* cc = (m ? coords2 : coords1) + (b * NN + n) * 3;
            g_cpack[m][b][n] = make_float4(cc[0], cc[1], cc[2], q);
        }
        float* sW1 = sbuf;            // 4096
        float* sW2 = sbuf + 4096;     // 320
        float* sb0 = sbuf + 4416;     // 64
        float* sb1 = sbuf + 4480;     // 64
        float* sb2 = sbuf + 4544;     // 8
        float* shh = sbuf + 4608;     // 8*64
        for (int k = tid; k < 4096; k += 256) sW1[k] = ppW1[k];
        for (int k = tid; k < 320; k += 256) sW2[k] = ppW2[k];
        if (tid < 64) { sb0[tid] = ppb0[tid]; sb1[tid] = ppb1[tid]; }
        if (tid < 5)  sb2[tid] = ppb2[tid];
        __syncthreads();
        int warp = tid >> 5, lane = tid & 31;
        float* hw = shh + warp * 64;
        for (int t = 0; t < 8; t++) {
            int p = bid * 64 + warp * 8 + t;        // < 16384
            int i = p >> 7, j = p & 127;
            float pr0 = 0, pr1 = 0, pr2 = 0, pr3 = 0, pr4 = 0;
            #pragma unroll
            for (int d = 0; d < 2; d++) {
                const float* U = d ? g_u[1][j] : g_u[0][i];
                const float* V = d ? g_v[0][i] : g_v[1][j];
                float2 uu = *(const float2*)(U + 2 * lane);
                float2 vv = *(const float2*)(V + 2 * lane);
                float h0 = milaf(uu.x + vv.x + sb0[2 * lane]);
                float h1 = milaf(uu.y + vv.y + sb0[2 * lane + 1]);
                __syncwarp();
                hw[2 * lane] = h0; hw[2 * lane + 1] = h1;
                __syncwarp();
                float a0 = sb1[2 * lane], a1 = sb1[2 * lane + 1];
                #pragma unroll 8
                for (int k = 0; k < 64; k++) {
                    float hk = hw[k];
                    float2 w = *(const float2*)(sW1 + k * 64 + 2 * lane);
                    a0 = fmaf(hk, w.x, a0);
                    a1 = fmaf(hk, w.y, a1);
                }
                float g0 = milaf(a0), g1 = milaf(a1);
                const float* w2a = sW2 + (2 * lane) * 5;
                const float* w2b = sW2 + (2 * lane + 1) * 5;
                float p0 = g0 * w2a[0] + g1 * w2b[0];
                float p1 = g0 * w2a[1] + g1 * w2b[1];
                float p2 = g0 * w2a[2] + g1 * w2b[2];
                float p3 = g0 * w2a[3] + g1 * w2b[3];
                float p4 = g0 * w2a[4] + g1 * w2b[4];
                p0 = wred(p0); p1 = wred(p1); p2 = wred(p2); p3 = wred(p3); p4 = wred(p4);
                pr0 += sspf(p0 + sb2[0]);
                pr1 += sspf(p1 + sb2[1]);
                pr2 += sspf(p2 + sb2[2]);
                pr3 += sspf(p3 + sb2[3]);
                pr4 += sspf(p4 + sb2[4]);
            }
            if (lane == 0) {
                float C6 = pr0, C8 = pr1, C10 = pr2, Act = pr3, bct = pr4;
                float r02 = C8 / (C6 + FEPS);
                float r3 = r02 * r02 * r02, r4 = r3 * r02, r5 = r4 * r02;
                float bd = sqrtf(g_ap[0][i][0] * g_ap[1][j][0]);
                float be = sqrtf(g_ap[0][i][4] * g_ap[1][j][4]);
                float Kp = g_ap[0][i][2] * g_ap[1][j][2];
                g_pp[0][p] = C6;  g_pp[1][p] = C8;  g_pp[2][p] = C10;
                g_pp[3][p] = r3;  g_pp[4][p] = r4;  g_pp[5][p] = r5;
                g_pp[6][p] = Act; g_pp[7][p] = bct; g_pp[8][p] = bd;
                g_pp[9][p] = be;  g_pp[10][p] = Kp;
            }
        }
    }
}

// ======= induction + energy: 2-CTA CLUSTER per batch, DSMEM mu exchange =======
// smem floats: c3s+c5s 33024, cp/mu/e0 6*512=3072, part 4096, fin 8  -> 40200
#define IND3_SMEM_FLOATS 40208

__global__ void __launch_bounds__(1024, 1) __cluster_dims__(2, 1, 1)
k_induct(const float* __restrict__ dist, float* __restrict__ out) {
    extern __shared__ float smem[];
    float*  c3s = smem;                       // [own atom row][other atom col], 129 pitch
    float*  c5s = smem + 16512;
    float4* cpO = (float4*)(smem + 33024);    // own cpack
    float4* cpX = cpO + 128;                  // other cpack
    float4* mu0 = cpX + 128;                  // own mu, buffer 0
    float4* mu1 = mu0 + 128;                  // own mu, buffer 1
    float4* muX = mu1 + 128;                  // staged peer mu
    float4* e0O = muX + 128;                  // own E0 (+pol in w)
    float4* part = (float4*)(e0O + 128);      // [8][128] slice partials / 1024 red
    float*  fin  = (float*)(part + 1024);     // 5 energy partials
    float*  ired = c3s;                       // reuse after iterations

    cg::cluster_group cl = cg::this_cluster();
    int half = (int)cl.block_rank();          // molecule this CTA owns
    int b = blockIdx.x >> 1;
    int tid = threadIdx.x;                    // 1024 threads

    float4* pMu0 = cl.map_shared_rank(mu0, half ^ 1);
    float4* pMu1 = cl.map_shared_rank(mu1, half ^ 1);
    float*  pFin = cl.map_shared_rank(fin, half ^ 1);

    if (tid < 128) {
        cpO[tid] = g_cpack[half][b][tid];
        cpX[tid] = g_cpack[half ^ 1][b][tid];
        float pol = g_ap[half][tid][1];
        e0O[tid] = make_float4(0.0f, 0.0f, 0.0f, pol);
    }
    __syncthreads();

    // ---- c3/c5 in own orientation (coalesced dist read; padded transpose OK) ----
    #pragma unroll
    for (int k = 0; k < 16; k++) {
        int p = tid + 1024 * k;
        int iA = p >> 7, jB = p & 127;
        float R = dist[b * NP + p];
        float polA = __ldg(&g_ap[0][iA][1]);
        float polB = __ldg(&g_ap[1][jB][1]);
        float au = sqrtf(polA * polB) + FEPS;
        float R2 = R * R;
        float r3raw = R2 * R;
        float u3 = __fdividef(r3raw, au);
        float exu = expf(SMEAR * u3);
        float lam3 = 1.0f - exu;
        float lam5 = 1.0f - (1.0f - SMEAR * u3) * exu;
        float c3v = __fdividef(lam3, r3raw + FEPS);
        float c5v = __fdividef(3.0f * lam5, R2 * r3raw + FEPS);
        int row = half ? jB : iA;
        int col = half ? iA : jB;
        c3s[row * 129 + col] = c3v;
        c5s[row * 129 + col] = c5v;
    }
    __syncthreads();

    // ---- warp map: 4 row-groups x 8 col-slices of 16 ----
    int w = tid >> 5, lane = tid & 31;
    int rg = w & 3;
    int slice = w >> 2;
    int row = rg * 32 + lane;                 // own atom 0..127
    int c0 = slice * 16;
    float4 cs = cpO[row];

    // ---- E0: E0_row = cs*sum(q c3) - sum(q c3 co) ----
    {
        float sk = 0, sx = 0, sy = 0, sz = 0;
        #pragma unroll 4
        for (int c = 0; c < 16; c++) {
            int oth = c0 + c;
            float c3 = c3s[row * 129 + oth];
            float4 co = cpX[oth];
            float wq = co.w * c3;
            sk += wq;
            sx = fmaf(wq, co.x, sx);
            sy = fmaf(wq, co.y, sy);
            sz = fmaf(wq, co.z, sz);
        }
        part[slice * 128 + row] = make_float4(fmaf(cs.x, sk, -sx),
                                              fmaf(cs.y, sk, -sy),
                                              fmaf(cs.z, sk, -sz), 0.0f);
    }
    __syncthreads();
    if (tid < 128) {
        float ex0 = 0, ey0 = 0, ez0 = 0;
        #pragma unroll
        for (int sl = 0; sl < 8; sl++) {
            float4 a = part[sl * 128 + tid];
            ex0 += a.x; ey0 += a.y; ez0 += a.z;
        }
        float pol = e0O[tid].w;
        e0O[tid] = make_float4(ex0, ey0, ez0, pol);
        float4 cc = cpO[tid];
        float mux = pol * ex0, muy = pol * ey0, muz = pol * ez0;
        float dcm = cc.x * mux + cc.y * muy + cc.z * muz;
        mu0[tid] = make_float4(mux, muy, muz, dcm);
    }
    __syncthreads();
    cl.sync();
    if (tid < 128) muX[tid] = pMu0[tid];      // DSMEM read of peer init mu
    __syncthreads();

    // ---- 8 fixed-point iterations: one cluster.sync each (double-buffered mu) ----
    for (int it = 0; it < 8; it++) {
        float sk = 0, sx = 0, sy = 0, sz = 0, tx = 0, ty = 0, tz = 0;
        #pragma unroll 4
        for (int c = 0; c < 16; c++) {
            int oth = c0 + c;
            float c3 = c3s[row * 129 + oth];
            float c5 = c5s[row * 129 + oth];
            float4 mo = muX[oth];
            float4 co = cpX[oth];
            float rm = fmaf(cs.x, mo.x, fmaf(cs.y, mo.y, fmaf(cs.z, mo.z, -mo.w)));
            float k5 = c5 * rm;
            sk += k5;
            sx = fmaf(k5, co.x, sx);
            sy = fmaf(k5, co.y, sy);
            sz = fmaf(k5, co.z, sz);
            tx = fmaf(c3, mo.x, tx);
            ty = fmaf(c3, mo.y, ty);
            tz = fmaf(c3, mo.z, tz);
        }
        part[slice * 128 + row] = make_float4(fmaf(cs.x, sk, -sx) - tx,
                                              fmaf(cs.y, sk, -sy) - ty,
                                              fmaf(cs.z, sk, -sz) - tz, 0.0f);
        __syncthreads();
        if (tid < 128) {
            float ax = 0, ay = 0, az = 0;
            #pragma unroll
            for (int sl = 0; sl < 8; sl++) {
                float4 a = part[sl * 128 + tid];
                ax += a.x; ay += a.y; az += a.z;
            }
            float4 e0 = e0O[tid];
            float4 mo = (it & 1) ? mu1[tid] : mu0[tid];     // previous own mu
            float pol = e0.w;
            float fx = e0.x + ax, fy = e0.y + ay, fz = e0.z + az;
            float mux = fmaf(0.75f * pol, fx, 0.25f * mo.x);
            float muy = fmaf(0.75f * pol, fy, 0.25f * mo.y);
            float muz = fmaf(0.75f * pol, fz, 0.25f * mo.z);
            float4 cc = cpO[tid];
            float dcm = cc.x * mux + cc.y * muy + cc.z * muz;
            float4 mv = make_float4(mux, muy, muz, dcm);
            if (it & 1) mu0[tid] = mv; else mu1[tid] = mv;  // write other buffer
        }
        __syncthreads();
        cl.sync();
        if (tid < 128) muX[tid] = (it & 1) ? pMu0[tid] : pMu1[tid];
        __syncthreads();
    }
    // own final mu in mu0 (it=7 odd wrote mu0); muX = peer final mu

    // ---- energy: this CTA handles its 8192 pairs ----
    const float4* muAp = half ? muX : mu0;
    const float4* muBp = half ? mu0 : muX;
    const float4* cpAp = half ? cpX : cpO;
    const float4* cpBp = half ? cpO : cpX;
    float es_a = 0, ex_a = 0, dsp_a = 0, ct_a = 0;
    #pragma unroll 4
    for (int k = 0; k < 8; k++) {
        int p = half * 8192 + tid + 1024 * k;
        int i = p >> 7, j = p & 127;
        float R = dist[b * NP + p];
        float C6  = __ldg(&g_pp[0][p]), C8  = __ldg(&g_pp[1][p]), C10 = __ldg(&g_pp[2][p]);
        float r3  = __ldg(&g_pp[3][p]), r4  = __ldg(&g_pp[4][p]), r5  = __ldg(&g_pp[5][p]);
        float Act = __ldg(&g_pp[6][p]), bct = __ldg(&g_pp[7][p]);
        float bd  = __ldg(&g_pp[8][p]), be  = __ldg(&g_pp[9][p]), Kp = __ldg(&g_pp[10][p]);
        float4 c1p = cpAp[i];
        float4 c2p = cpBp[j];
        float4 m1 = muAp[i];
        float4 m2 = muBp[j];
        float B0 = __fdividef(1.0f, R + FEPS);
        float ebd = expf(-bd * R);
        es_a += c1p.w * c2p.w * (1.0f - fmaf(0.5f * bd, R, 1.0f) * ebd) * B0;
        ct_a += Act * expf(-bct * R);
        float R2 = R * R;
        if (R2 < 2500.0f) {
            float R6 = R2 * R2 * R2;
            float R8 = R6 * R2;
            float R10 = R8 * R2;
            dsp_a -= __fdividef(C6, R6 + r3) + __fdividef(C8, R8 + r4) + __fdividef(C10, R10 + r5);
        }
        float rhx = (c2p.x - c1p.x) * B0;
        float rhy = (c2p.y - c1p.y) * B0;
        float rhz = (c2p.z - c1p.z) * B0;
        float proj = (m1.x - m2.x) * rhx + (m1.y - m2.y) * rhy + (m1.z - m2.z) * rhz;
        float qe1 = __ldg(&g_qe[0][b][i]);
        float qe2 = __ldg(&g_qe[1][b][j]);
        ex_a += Kp * qe1 * qe2 * (1.0f + proj) * expf(-be * R) * B0;
    }
    float iev = 0.0f;
    if (tid < 128) {
        float4 mo = mu0[tid];
        float4 e0 = e0O[tid];
        iev = mo.x * e0.x + mo.y * e0.y + mo.z * e0.z;
    }
    __syncthreads();
    part[tid] = make_float4(es_a, ex_a, dsp_a, ct_a);
    ired[tid] = iev;
    __syncthreads();
    for (int s = 512; s; s >>= 1) {
        if (tid < s) {
            float4 a = part[tid], c = part[tid + s];
            part[tid] = make_float4(a.x + c.x, a.y + c.y, a.z + c.z, a.w + c.w);
            ired[tid] += ired[tid + s];
        }
        __syncthreads();
    }
    if (tid == 0) {
        float4 a = part[0];
        fin[0] = a.x; fin[1] = a.y; fin[2] = a.z; fin[3] = a.w; fin[4] = ired[0];
    }
    __syncthreads();
    cl.sync();
    if (half == 0 && tid == 0) {
        float es  = fin[0] + pFin[0];
        float ex  = fin[1] + pFin[1];
        float dsp = fin[2] + pFin[2];
        float ct  = fin[3] + pFin[3];
        float ie  = fin[4] + pFin[4];
        float in_t = -0.5f * ie - ct;
        out[b]        = ex + dsp + es + in_t;
        out[64 + b]   = es;
        out[128 + b]  = in_t;
        out[192 + b]  = ex;
        out[256 + b]  = dsp;
    }
    cl.sync();     // no CTA exits while peer may still read its smem
}

// ---------------- launch ----------------
extern "C" void kernel_launch(void* const* d_in, const int* in_sizes, int n_in,
                              void* d_out, int out_size) {
    const float* nodes1    = (const float*)d_in[0];
    const float* edges1    = (const float*)d_in[1];
    const int*   senders1  = (const int*)d_in[2];
    const int*   receivers1= (const int*)d_in[3];
    const float* nodes2    = (const float*)d_in[4];
    const float* edges2    = (const float*)d_in[5];
    const int*   senders2  = (const int*)d_in[6];
    const int*   receivers2= (const int*)d_in[7];
    const float* coords1   = (const float*)d_in[8];
    const float* coords2   = (const float*)d_in[9];
    const float* dist;
    const float* mp;
    if (in_sizes[10] == 2 * BB * NN) {        // multipoles came first
        mp   = (const float*)d_in[10];
        dist = (const float*)d_in[11];
    } else {                                  // distance_matrices first (setup order)
        dist = (const float*)d_in[10];
        mp   = (const float*)d_in[11];
    }
    const float* W_emb_node = (const float*)d_in[12];
    const float* b_emb_node = (const float*)d_in[13];
    const float* W_emb_edge = (const float*)d_in[14];
    const float* b_emb_edge = (const float*)d_in[15];
    const float* W_gn_edge  = (const float*)d_in[16];
    const float* b_gn_edge  = (const float*)d_in[17];
    const float* W_gn_node  = (const float*)d_in[18];
    const float* b_gn_node  = (const float*)d_in[19];
    const float* pp_W0 = (const float*)d_in[20];
    const float* pp_b0 = (const float*)d_in[21];
    const float* pp_W1 = (const float*)d_in[22];
    const float* pp_b1 = (const float*)d_in[23];
    const float* pp_W2 = (const float*)d_in[24];
    const float* pp_b2 = (const float*)d_in[25];
    const float* ap_W0 = (const float*)d_in[26];
    const float* ap_b0 = (const float*)d_in[27];
    const float* ap_W1 = (const float*)d_in[28];
    const float* ap_b1 = (const float*)d_in[29];
    const float* ap_W2 = (const float*)d_in[30];
    const float* ap_b2 = (const float*)d_in[31];
    float* out = (float*)d_out;

    static int smem_set = 0;
    if (!smem_set) {
        cudaFuncSetAttribute(k_induct, cudaFuncAttributeMaxDynamicSharedMemorySize,
                             IND3_SMEM_FLOATS * 4);
        smem_set = 1;
    }

    k_gnn<<<NBLK, 256>>>(nodes1, nodes2, edges1, edges2,
                         senders1, receivers1, senders2, receivers2,
                         W_emb_node, b_emb_node, W_emb_edge, b_emb_edge,
                         W_gn_edge, b_gn_edge, W_gn_node, b_gn_node,
                         ap_W0, ap_b0, ap_W1, ap_b1, ap_W2, ap_b2,
                         pp_W0, pp_b0, pp_W1, pp_b1, pp_W2, pp_b2,
                         mp, coords1, coords2);
    k_induct<<<2 * BB, 1024, IND3_SMEM_FLOATS * 4>>>(dist, out);
}

// round 17
// speedup vs baseline: 1.6936x; 1.0300x over previous
#include <cuda_runtime.h>
#include <cuda_pipeline.h>
#include <cooperative_groups.h>
#include <math.h>

namespace cg = cooperative_groups;

#define NN   128
#define NE   512
#define HID  64
#define BB   64
#define NP   16384     // NN*NN
#define SMEAR (-0.39f)
#define FEPS  1e-6f
#define NBLK 256       // persistent grid: 2 blocks/SM, all resident

// ---------------- device scratch (no allocation allowed) ----------------
__device__ float  g_n[2][2][NN][HID];     // [pingpong][mol][node][feat]
__device__ float  g_e[2][2][NE][HID];     // [pingpong][mol][edge][feat]
__device__ int    g_h[2][NN];
__device__ int    g_cnt[2][NN];
__device__ short  g_elist[2][NN][NE];
__device__ float  g_ap[2][NN][5];         // a_d, pol, K, dq, a_e
__device__ float  g_u[2][NN][HID];        // feats @ ppW0[0:64]
__device__ float  g_v[2][NN][HID];        // feats @ ppW0[64:128]
__device__ float  g_pp[11][NP];           // C6,C8,C10,r3,r4,r5,Act,bct,bd,be,Kp
__device__ float4 g_cpack[2][BB][NN];     // (cx,cy,cz,q)
__device__ float  g_qe[2][BB][NN];
__device__ int           g_bar_count;     // self-resetting
__device__ volatile int  g_bar_gen;       // monotonic generation

// mila(x) = x * tanh(softplus(x-1)) = x * (1 - 2/((1+e^{x-1})^2 + 1))  (exact)
__device__ __forceinline__ float milaf(float x) {
    float t = expf(x - 1.0f);
    float a = 1.0f + t;
    float d = fmaf(a, a, 1.0f);
    return x * (1.0f - __fdividef(2.0f, d));
}
__device__ __forceinline__ float sspf(float x) {
    return fmaxf(x, 0.0f) + log1pf(expf(-fabsf(x))) + 0.001f;
}
__device__ __forceinline__ float wred(float v) {
    #pragma unroll
    for (int o = 16; o; o >>= 1) v += __shfl_xor_sync(0xffffffffu, v, o);
    return v;
}

// grid barrier: release fence per thread; acquire-side IVALL from tid0 only.
__device__ __forceinline__ void gridbar() {
    __threadfence();
    __syncthreads();
    if (threadIdx.x == 0) {
        int gen = g_bar_gen;
        if (atomicAdd(&g_bar_count, 1) == NBLK - 1) {
            g_bar_count = 0;
            __threadfence();
            g_bar_gen = gen + 1;
        } else {
            while (g_bar_gen == gen) __nanosleep(64);
        }
        __threadfence();
    }
    __syncthreads();
}

// async copy of nf4 float4 chunks (256-thread cooperative)
__device__ __forceinline__ void acopy(float* dst, const float* src, int nf4) {
    float4* d = (float4*)dst;
    const float4* s = (const float4*)src;
    for (int k = threadIdx.x; k < nf4; k += 256)
        __pipeline_memcpy_async(d + k, s + k, 16);
}

// ================= persistent GNN + pair mega-kernel =================
// dynamic smem: eW 12288 | nW 8192 | sx 512  (83968 B)
#define GNN_SMEM_FLOATS (12288 + 8192 + 512)

__global__ void __launch_bounds__(256) k_gnn(
        const float* __restrict__ nodes1, const float* __restrict__ nodes2,
        const float* __restrict__ edges1, const float* __restrict__ edges2,
        const int* __restrict__ snd1, const int* __restrict__ rcv1,
        const int* __restrict__ snd2, const int* __restrict__ rcv2,
        const float* __restrict__ Wn, const float* __restrict__ bn,
        const float* __restrict__ We, const float* __restrict__ be_,
        const float* __restrict__ Wge, const float* __restrict__ bge,
        const float* __restrict__ Wgn, const float* __restrict__ bgn,
        const float* __restrict__ apW0, const float* __restrict__ apb0,
        const float* __restrict__ apW1, const float* __restrict__ apb1,
        const float* __restrict__ apW2, const float* __restrict__ apb2,
        const float* __restrict__ ppW0, const float* __restrict__ ppb0,
        const float* __restrict__ ppW1, const float* __restrict__ ppb1,
        const float* __restrict__ ppW2, const float* __restrict__ ppb2,
        const float* __restrict__ mp,
        const float* __restrict__ coords1, const float* __restrict__ coords2) {
    extern __shared__ float sbuf[];
    float* eW = sbuf;             // 12288 floats (48KB)
    float* nW = sbuf + 12288;     // 8192 floats (32KB)
    float* sx = sbuf + 20480;     // 512 floats
    int tid = threadIdx.x;
    int bid = blockIdx.x;

    // G0: edge W step0 + node W step0
    acopy(eW, Wge, 3072);
    acopy(nW, Wgn, 2048);
    __pipeline_commit();

    // ---------- P0: embed (255 blocks) + CSR build (block 255) ----------
    if (bid == NBLK - 1) {
        int m = tid >> 7, node = tid & 127;
        const int* rcv = m ? rcv2 : rcv1;
        int c = 0;
        for (int e = 0; e < NE; e++) {
            if (rcv[e] == node) g_elist[m][node][c++] = (short)e;
        }
        g_cnt[m][node] = c;
    } else {
        for (int g = bid * 256 + tid; g < 2 * NN * HID + 2 * NE * HID + 2 * NN;
             g += (NBLK - 1) * 256) {
            if (g < 2 * NN * HID) {
                int m = g / (NN * HID);
                int r = g % (NN * HID);
                int i = r / HID, o = r % HID;
                const float* nd = m ? nodes2 : nodes1;
                float acc = bn[o];
                #pragma unroll
                for (int k = 0; k < 16; k++)
                    acc = fmaf(nd[i * 16 + k], __ldg(Wn + k * HID + o), acc);
                g_n[0][m][i][o] = milaf(acc);
            } else if (g < 2 * NN * HID + 2 * NE * HID) {
                int r = g - 2 * NN * HID;
                int m = r / (NE * HID);
                r %= NE * HID;
                int ei = r / HID, o = r % HID;
                const float* ed = m ? edges2 : edges1;
                float acc = be_[o];
                #pragma unroll
                for (int k = 0; k < 8; k++)
                    acc = fmaf(ed[ei * 8 + k], __ldg(We + k * HID + o), acc);
                g_e[0][m][ei][o] = milaf(acc);
            } else {
                int r = g - (2 * NN * HID + 2 * NE * HID);
                int m = r >> 7, i = r & 127;
                const float* nd = m ? nodes2 : nodes1;
                float v0 = nd[i * 16];
                float mx = -1e30f;
                #pragma unroll
                for (int k = 1; k < 16; k++) mx = fmaxf(mx, nd[i * 16 + k]);
                g_h[m][i] = (v0 >= mx) ? 1 : 0;
            }
        }
    }
    gridbar();

    // ---------- message-passing steps ----------
    int ib = 0;
    for (int s = 0; s < 3; s++) {
        int ob = 1 - ib;

        // ----- edge phase: 256 blocks x 256 items -----
        {
            if (s > 0) {                       // prefetch node W for this step
                acopy(nW, Wgn + s * 8192, 2048);
                __pipeline_commit();
                __pipeline_wait_prior(1);      // edge W (committed last phase) ready
            } else {
                __pipeline_wait_prior(0);      // G0 ready
            }
            __syncthreads();
            int g = bid * 256 + tid;
            int m = g >> 15;
            int r = g & 32767;
            int e = r >> 6, o = r & 63;
            const int* snd = m ? snd2 : snd1;
            const int* rcv = m ? rcv2 : rcv1;
            int sidx = snd[e], ridx = rcv[e];
            const float4* er = (const float4*)&g_e[ib][m][e][0];
            const float4* nr = (const float4*)&g_n[ib][m][ridx][0];
            const float4* ns = (const float4*)&g_n[ib][m][sidx][0];
            float acc1 = bge[s * 64 + o];
            float acc2 = 0.0f;
            float acc3 = 0.0f;
            #pragma unroll 4
            for (int c = 0; c < 16; c++) {
                float4 ev = er[c], rv = nr[c], sv = ns[c];
                int k4 = 4 * c;
                acc1 = fmaf(ev.x, eW[(k4 + 0) * 64 + o], acc1);
                acc2 = fmaf(rv.x, eW[(64 + k4 + 0) * 64 + o], acc2);
                acc3 = fmaf(sv.x, eW[(128 + k4 + 0) * 64 + o], acc3);
                acc1 = fmaf(ev.y, eW[(k4 + 1) * 64 + o], acc1);
                acc2 = fmaf(rv.y, eW[(64 + k4 + 1) * 64 + o], acc2);
                acc3 = fmaf(sv.y, eW[(128 + k4 + 1) * 64 + o], acc3);
                acc1 = fmaf(ev.z, eW[(k4 + 2) * 64 + o], acc1);
                acc2 = fmaf(rv.z, eW[(64 + k4 + 2) * 64 + o], acc2);
                acc3 = fmaf(sv.z, eW[(128 + k4 + 2) * 64 + o], acc3);
                acc1 = fmaf(ev.w, eW[(k4 + 3) * 64 + o], acc1);
                acc2 = fmaf(rv.w, eW[(64 + k4 + 3) * 64 + o], acc2);
                acc3 = fmaf(sv.w, eW[(128 + k4 + 3) * 64 + o], acc3);
            }
            g_e[ob][m][e][o] = milaf(acc1 + acc2 + acc3);
        }
        gridbar();

        // ----- node phase: blocks 0..127, 2 nodes per block -----
        {
            if (s < 2) {                       // prefetch next edge W
                acopy(eW, Wge + (s + 1) * 12288, 3072);
            } else {                           // prefetch pair W1 into edge area
                acopy(eW, ppW1, 1024);
            }
            __pipeline_commit();
            __pipeline_wait_prior(1);          // node W ready
            __syncthreads();
            if (bid < 128) {
                float* sagg = sx;
                float* sf   = sx + 128;
                float* sh1  = sx + 256;
                float* sh2  = sx + 384;
                int g = bid * 128 + tid;       // valid for tid<128
                int m = g >> 13;
                int i = (g >> 6) & 127;
                int o = g & 63;
                int nl = (tid >> 6) & 1;
                if (tid < 128) {
                    int cnt = g_cnt[m][i];
                    float agg = 0.0f;
                    for (int c = 0; c < cnt; c++) agg += g_e[ob][m][g_elist[m][i][c]][o];
                    sagg[tid] = agg;
                }
                __syncthreads();
                float val = 0.0f;
                if (tid < 128) {
                    const float4* nr = (const float4*)&g_n[ib][m][i][0];
                    const float4* ar = (const float4*)&sagg[nl * 64];
                    float acc1 = bgn[s * 64 + o];
                    float acc2 = 0.0f;
                    #pragma unroll 4
                    for (int c = 0; c < 16; c++) {
                        float4 nv = nr[c], av = ar[c];
                        int k4 = 4 * c;
                        acc1 = fmaf(nv.x, nW[(k4 + 0) * 64 + o], acc1);
                        acc2 = fmaf(av.x, nW[(64 + k4 + 0) * 64 + o], acc2);
                        acc1 = fmaf(nv.y, nW[(k4 + 1) * 64 + o], acc1);
                        acc2 = fmaf(av.y, nW[(64 + k4 + 1) * 64 + o], acc2);
                        acc1 = fmaf(nv.z, nW[(k4 + 2) * 64 + o], acc1);
                        acc2 = fmaf(av.z, nW[(64 + k4 + 2) * 64 + o], acc2);
                        acc1 = fmaf(nv.w, nW[(k4 + 3) * 64 + o], acc1);
                        acc2 = fmaf(av.w, nW[(64 + k4 + 3) * 64 + o], acc2);
                    }
                    val = milaf(acc1 + acc2);
                    g_n[ob][m][i][o] = val;
                }
                if (s == 2) {   // fused post: atom props + pair-layer-0 factorization
                    if (tid < 128) sf[tid] = val;
                    __syncthreads();
                    if (tid < 128) {
                        const float* f = &sf[nl * 64];
                        float a = apb0[o], su = 0.0f, sv = 0.0f;
                        #pragma unroll 8
                        for (int k = 0; k < 64; k++) {
                            float fk = f[k];
                            a  = fmaf(fk, __ldg(apW0 + k * 64 + o), a);
                            su = fmaf(fk, __ldg(ppW0 + k * 64 + o), su);
                            sv = fmaf(fk, __ldg(ppW0 + (64 + k) * 64 + o), sv);
                        }
                        sh1[tid] = milaf(a);
                        g_u[m][i][o] = su;
                        g_v[m][i][o] = sv;
                    }
                    __syncthreads();
                    if (tid < 128) {
                        float a1 = apb1[o];
                        const float* h1 = &sh1[nl * 64];
                        #pragma unroll 8
                        for (int k = 0; k < 64; k++)
                            a1 = fmaf(h1[k], __ldg(apW1 + k * 64 + o), a1);
                        sh2[tid] = milaf(a1);
                    }
                    __syncthreads();
                    if (tid < 128 && o < 5) {
                        float a2 = apb2[o];
                        const float* h2 = &sh2[nl * 64];
                        for (int k = 0; k < 64; k++)
                            a2 = fmaf(h2[k], __ldg(apW2 + k * 5 + o), a2);
                        g_ap[m][i][o] = sspf(a2);
                    }
                }
            }
        }
        gridbar();
        ib = ob;
    }

    // ---------- pair phase: 256 blocks x 64 pairs (W1 already in eW) ----------
    {
        int idx = bid * 256 + tid;
        if (idx < 2 * BB * NN) {
            int m = idx >> 13;
            int r = idx & 8191;
            int b = r >> 7, n = r & 127;
            float q = mp[(m * BB + b) * NN + n];
            float dq = g_ap[m][n][3];
            float qe = g_h[m][n] ? (1.0f - q) : (2.0f + dq - q);
            g_qe[m][b][n] = qe;
            const float* cc = (m ? coords2 : coords1) + (b * NN + n) * 3;
            g_cpack[m][b][n] = make_float4(cc[0], cc[1], cc[2], q);
        }
        float* sW1 = eW;              // 4096 (async-copied during node2)
        float* sW2 = nW;              // 320
        float* sb0 = nW + 320;
        float* sb1 = nW + 384;
        float* sb2 = nW + 448;
        float* shh = nW + 512;        // 8*64
        for (int k = tid; k < 320; k += 256) sW2[k] = ppW2[k];
        if (tid < 64) { sb0[tid] = ppb0[tid]; sb1[tid] = ppb1[tid]; }
        if (tid < 5)  sb2[tid] = ppb2[tid];
        __pipeline_wait_prior(0);     // W1 ready
        __syncthreads();
        int warp = tid >> 5, lane = tid & 31;
        float* hw = shh + warp * 64;
        for (int t = 0; t < 8; t++) {
            int p = bid * 64 + warp * 8 + t;        // < 16384
            int i = p >> 7, j = p & 127;
            float pr0 = 0, pr1 = 0, pr2 = 0, pr3 = 0, pr4 = 0;
            #pragma unroll
            for (int d = 0; d < 2; d++) {
                const float* U = d ? g_u[1][j] : g_u[0][i];
                const float* V = d ? g_v[0][i] : g_v[1][j];
                float2 uu = *(const float2*)(U + 2 * lane);
                float2 vv = *(const float2*)(V + 2 * lane);
                float h0 = milaf(uu.x + vv.x + sb0[2 * lane]);
                float h1 = milaf(uu.y + vv.y + sb0[2 * lane + 1]);
                __syncwarp();
                hw[2 * lane] = h0; hw[2 * lane + 1] = h1;
                __syncwarp();
                float a0 = sb1[2 * lane], a1 = sb1[2 * lane + 1];
                #pragma unroll 8
                for (int k = 0; k < 64; k++) {
                    float hk = hw[k];
                    float2 w = *(const float2*)(sW1 + k * 64 + 2 * lane);
                    a0 = fmaf(hk, w.x, a0);
                    a1 = fmaf(hk, w.y, a1);
                }
                float g0 = milaf(a0), g1 = milaf(a1);
                const float* w2a = sW2 + (2 * lane) * 5;
                const float* w2b = sW2 + (2 * lane + 1) * 5;
                float p0 = g0 * w2a[0] + g1 * w2b[0];
                float p1 = g0 * w2a[1] + g1 * w2b[1];
                float p2 = g0 * w2a[2] + g1 * w2b[2];
                float p3 = g0 * w2a[3] + g1 * w2b[3];
                float p4 = g0 * w2a[4] + g1 * w2b[4];
                p0 = wred(p0); p1 = wred(p1); p2 = wred(p2); p3 = wred(p3); p4 = wred(p4);
                pr0 += sspf(p0 + sb2[0]);
                pr1 += sspf(p1 + sb2[1]);
                pr2 += sspf(p2 + sb2[2]);
                pr3 += sspf(p3 + sb2[3]);
                pr4 += sspf(p4 + sb2[4]);
            }
            if (lane == 0) {
                float C6 = pr0, C8 = pr1, C10 = pr2, Act = pr3, bct = pr4;
                float r02 = C8 / (C6 + FEPS);
                float r3 = r02 * r02 * r02, r4 = r3 * r02, r5 = r4 * r02;
                float bd = sqrtf(g_ap[0][i][0] * g_ap[1][j][0]);
                float be = sqrtf(g_ap[0][i][4] * g_ap[1][j][4]);
                float Kp = g_ap[0][i][2] * g_ap[1][j][2];
                g_pp[0][p] = C6;  g_pp[1][p] = C8;  g_pp[2][p] = C10;
                g_pp[3][p] = r3;  g_pp[4][p] = r4;  g_pp[5][p] = r5;
                g_pp[6][p] = Act; g_pp[7][p] = bct; g_pp[8][p] = bd;
                g_pp[9][p] = be;  g_pp[10][p] = Kp;
            }
        }
    }
}

// ======= induction + energy: 2-CTA CLUSTER per batch, DSMEM mu exchange =======
// smem floats: c35 33024, cp/mu/e0 6*512=3072, part 4096, fin 8 -> 40200 (pad 40208)
#define IND3_SMEM_FLOATS 40208

__global__ void __launch_bounds__(1024, 1) __cluster_dims__(2, 1, 1)
k_induct(const float* __restrict__ dist, float* __restrict__ out) {
    extern __shared__ float smem[];
    float2* c35 = (float2*)smem;              // [own row][other col], pitch 129
    float4* cpO = (float4*)(smem + 33024);
    float4* cpX = cpO + 128;
    float4* mu0 = cpX + 128;
    float4* mu1 = mu0 + 128;
    float4* muX = mu1 + 128;
    float4* e0O = muX + 128;
    float4* part = (float4*)(e0O + 128);
    float*  fin  = (float*)(part + 1024);
    float*  ired = smem;                      // reuse after iterations

    cg::cluster_group cl = cg::this_cluster();
    int half = (int)cl.block_rank();
    int b = blockIdx.x >> 1;
    int tid = threadIdx.x;

    float4* pMu0 = cl.map_shared_rank(mu0, half ^ 1);
    float4* pMu1 = cl.map_shared_rank(mu1, half ^ 1);
    float*  pFin = cl.map_shared_rank(fin, half ^ 1);

    if (tid < 128) {
        cpO[tid] = g_cpack[half][b][tid];
        cpX[tid] = g_cpack[half ^ 1][b][tid];
        float pol = g_ap[half][tid][1];
        e0O[tid] = make_float4(0.0f, 0.0f, 0.0f, pol);
    }
    __syncthreads();

    #pragma unroll
    for (int k = 0; k < 16; k++) {
        int p = tid + 1024 * k;
        int iA = p >> 7, jB = p & 127;
        float R = dist[b * NP + p];
        float polA = __ldg(&g_ap[0][iA][1]);
        float polB = __ldg(&g_ap[1][jB][1]);
        float au = sqrtf(polA * polB) + FEPS;
        float R2 = R * R;
        float r3raw = R2 * R;
        float u3 = __fdividef(r3raw, au);
        float exu = expf(SMEAR * u3);
        float lam3 = 1.0f - exu;
        float lam5 = 1.0f - (1.0f - SMEAR * u3) * exu;
        float c3v = __fdividef(lam3, r3raw + FEPS);
        float c5v = __fdividef(3.0f * lam5, R2 * r3raw + FEPS);
        int row = half ? jB : iA;
        int col = half ? iA : jB;
        c35[row * 129 + col] = make_float2(c3v, c5v);
    }
    __syncthreads();

    int w = tid >> 5, lane = tid & 31;
    int rg = w & 3;
    int slice = w >> 2;
    int row = rg * 32 + lane;
    int c0 = slice * 16;
    float4 cs = cpO[row];

    {
        float sk = 0, sx = 0, sy = 0, sz = 0;
        #pragma unroll 4
        for (int c = 0; c < 16; c++) {
            int oth = c0 + c;
            float c3 = c35[row * 129 + oth].x;
            float4 co = cpX[oth];
            float wq = co.w * c3;
            sk += wq;
            sx = fmaf(wq, co.x, sx);
            sy = fmaf(wq, co.y, sy);
            sz = fmaf(wq, co.z, sz);
        }
        part[slice * 128 + row] = make_float4(fmaf(cs.x, sk, -sx),
                                              fmaf(cs.y, sk, -sy),
                                              fmaf(cs.z, sk, -sz), 0.0f);
    }
    __syncthreads();
    if (tid < 128) {
        float ex0 = 0, ey0 = 0, ez0 = 0;
        #pragma unroll
        for (int sl = 0; sl < 8; sl++) {
            float4 a = part[sl * 128 + tid];
            ex0 += a.x; ey0 += a.y; ez0 += a.z;
        }
        float pol = e0O[tid].w;
        e0O[tid] = make_float4(ex0, ey0, ez0, pol);
        float4 cc = cpO[tid];
        float mux = pol * ex0, muy = pol * ey0, muz = pol * ez0;
        float dcm = cc.x * mux + cc.y * muy + cc.z * muz;
        mu0[tid] = make_float4(mux, muy, muz, dcm);
    }
    __syncthreads();
    cl.sync();
    if (tid < 128) muX[tid] = pMu0[tid];
    __syncthreads();

    for (int it = 0; it < 8; it++) {
        float sk = 0, sx = 0, sy = 0, sz = 0, tx = 0, ty = 0, tz = 0;
        #pragma unroll 4
        for (int c = 0; c < 16; c++) {
            int oth = c0 + c;
            float2 cv = c35[row * 129 + oth];
            float4 mo = muX[oth];
            float4 co = cpX[oth];
            float rm = fmaf(cs.x, mo.x, fmaf(cs.y, mo.y, fmaf(cs.z, mo.z, -mo.w)));
            float k5 = cv.y * rm;
            sk += k5;
            sx = fmaf(k5, co.x, sx);
            sy = fmaf(k5, co.y, sy);
            sz = fmaf(k5, co.z, sz);
            tx = fmaf(cv.x, mo.x, tx);
            ty = fmaf(cv.x, mo.y, ty);
            tz = fmaf(cv.x, mo.z, tz);
        }
        part[slice * 128 + row] = make_float4(fmaf(cs.x, sk, -sx) - tx,
                                              fmaf(cs.y, sk, -sy) - ty,
                                              fmaf(cs.z, sk, -sz) - tz, 0.0f);
        __syncthreads();
        if (tid < 128) {
            float ax = 0, ay = 0, az = 0;
            #pragma unroll
            for (int sl = 0; sl < 8; sl++) {
                float4 a = part[sl * 128 + tid];
                ax += a.x; ay += a.y; az += a.z;
            }
            float4 e0 = e0O[tid];
            float4 mo = (it & 1) ? mu1[tid] : mu0[tid];
            float pol = e0.w;
            float fx = e0.x + ax, fy = e0.y + ay, fz = e0.z + az;
            float mux = fmaf(0.75f * pol, fx, 0.25f * mo.x);
            float muy = fmaf(0.75f * pol, fy, 0.25f * mo.y);
            float muz = fmaf(0.75f * pol, fz, 0.25f * mo.z);
            float4 cc = cpO[tid];
            float dcm = cc.x * mux + cc.y * muy + cc.z * muz;
            float4 mv = make_float4(mux, muy, muz, dcm);
            if (it & 1) mu0[tid] = mv; else mu1[tid] = mv;
        }
        __syncthreads();
        cl.sync();
        if (tid < 128) muX[tid] = (it & 1) ? pMu0[tid] : pMu1[tid];
        __syncthreads();
    }

    const float4* muAp = half ? muX : mu0;
    const float4* muBp = half ? mu0 : muX;
    const float4* cpAp = half ? cpX : cpO;
    const float4* cpBp = half ? cpO : cpX;
    float es_a = 0, ex_a = 0, dsp_a = 0, ct_a = 0;
    #pragma unroll 4
    for (int k = 0; k < 8; k++) {
        int p = half * 8192 + tid + 1024 * k;
        int i = p >> 7, j = p & 127;
        float R = dist[b * NP + p];
        float C6  = __ldg(&g_pp[0][p]), C8  = __ldg(&g_pp[1][p]), C10 = __ldg(&g_pp[2][p]);
        float r3  = __ldg(&g_pp[3][p]), r4  = __ldg(&g_pp[4][p]), r5  = __ldg(&g_pp[5][p]);
        float Act = __ldg(&g_pp[6][p]), bct = __ldg(&g_pp[7][p]);
        float bd  = __ldg(&g_pp[8][p]), be  = __ldg(&g_pp[9][p]), Kp = __ldg(&g_pp[10][p]);
        float4 c1p = cpAp[i];
        float4 c2p = cpBp[j];
        float4 m1 = muAp[i];
        float4 m2 = muBp[j];
        float B0 = __fdividef(1.0f, R + FEPS);
        float ebd = expf(-bd * R);
        es_a += c1p.w * c2p.w * (1.0f - fmaf(0.5f * bd, R, 1.0f) * ebd) * B0;
        ct_a += Act * expf(-bct * R);
        float R2 = R * R;
        if (R2 < 2500.0f) {
            float R6 = R2 * R2 * R2;
            float R8 = R6 * R2;
            float R10 = R8 * R2;
            dsp_a -= __fdividef(C6, R6 + r3) + __fdividef(C8, R8 + r4) + __fdividef(C10, R10 + r5);
        }
        float rhx = (c2p.x - c1p.x) * B0;
        float rhy = (c2p.y - c1p.y) * B0;
        float rhz = (c2p.z - c1p.z) * B0;
        float proj = (m1.x - m2.x) * rhx + (m1.y - m2.y) * rhy + (m1.z - m2.z) * rhz;
        float qe1 = __ldg(&g_qe[0][b][i]);
        float qe2 = __ldg(&g_qe[1][b][j]);
        ex_a += Kp * qe1 * qe2 * (1.0f + proj) * expf(-be * R) * B0;
    }
    float iev = 0.0f;
    if (tid < 128) {
        float4 mo = mu0[tid];
        float4 e0 = e0O[tid];
        iev = mo.x * e0.x + mo.y * e0.y + mo.z * e0.z;
    }
    __syncthreads();
    part[tid] = make_float4(es_a, ex_a, dsp_a, ct_a);
    ired[tid] = iev;
    __syncthreads();
    for (int s = 512; s; s >>= 1) {
        if (tid < s) {
            float4 a = part[tid], c = part[tid + s];
            part[tid] = make_float4(a.x + c.x, a.y + c.y, a.z + c.z, a.w + c.w);
            ired[tid] += ired[tid + s];
        }
        __syncthreads();
    }
    if (tid == 0) {
        float4 a = part[0];
        fin[0] = a.x; fin[1] = a.y; fin[2] = a.z; fin[3] = a.w; fin[4] = ired[0];
    }
    __syncthreads();
    cl.sync();
    if (half == 0 && tid == 0) {
        float es  = fin[0] + pFin[0];
        float ex  = fin[1] + pFin[1];
        float dsp = fin[2] + pFin[2];
        float ct  = fin[3] + pFin[3];
        float ie  = fin[4] + pFin[4];
        float in_t = -0.5f * ie - ct;
        out[b]        = ex + dsp + es + in_t;
        out[64 + b]   = es;
        out[128 + b]  = in_t;
        out[192 + b]  = ex;
        out[256 + b]  = dsp;
    }
    cl.sync();
}

// ---------------- launch ----------------
extern "C" void kernel_launch(void* const* d_in, const int* in_sizes, int n_in,
                              void* d_out, int out_size) {
    const float* nodes1    = (const float*)d_in[0];
    const float* edges1    = (const float*)d_in[1];
    const int*   senders1  = (const int*)d_in[2];
    const int*   receivers1= (const int*)d_in[3];
    const float* nodes2    = (const float*)d_in[4];
    const float* edges2    = (const float*)d_in[5];
    const int*   senders2  = (const int*)d_in[6];
    const int*   receivers2= (const int*)d_in[7];
    const float* coords1   = (const float*)d_in[8];
    const float* coords2   = (const float*)d_in[9];
    const float* dist;
    const float* mp;
    if (in_sizes[10] == 2 * BB * NN) {        // multipoles came first
        mp   = (const float*)d_in[10];
        dist = (const float*)d_in[11];
    } else {                                  // distance_matrices first (setup order)
        dist = (const float*)d_in[10];
        mp   = (const float*)d_in[11];
    }
    const float* W_emb_node = (const float*)d_in[12];
    const float* b_emb_node = (const float*)d_in[13];
    const float* W_emb_edge = (const float*)d_in[14];
    const float* b_emb_edge = (const float*)d_in[15];
    const float* W_gn_edge  = (const float*)d_in[16];
    const float* b_gn_edge  = (const float*)d_in[17];
    const float* W_gn_node  = (const float*)d_in[18];
    const float* b_gn_node  = (const float*)d_in[19];
    const float* pp_W0 = (const float*)d_in[20];
    const float* pp_b0 = (const float*)d_in[21];
    const float* pp_W1 = (const float*)d_in[22];
    const float* pp_b1 = (const float*)d_in[23];
    const float* pp_W2 = (const float*)d_in[24];
    const float* pp_b2 = (const float*)d_in[25];
    const float* ap_W0 = (const float*)d_in[26];
    const float* ap_b0 = (const float*)d_in[27];
    const float* ap_W1 = (const float*)d_in[28];
    const float* ap_b1 = (const float*)d_in[29];
    const float* ap_W2 = (const float*)d_in[30];
    const float* ap_b2 = (const float*)d_in[31];
    float* out = (float*)d_out;

    static int smem_set = 0;
    if (!smem_set) {
        cudaFuncSetAttribute(k_gnn, cudaFuncAttributeMaxDynamicSharedMemorySize,
                             GNN_SMEM_FLOATS * 4);
        cudaFuncSetAttribute(k_induct, cudaFuncAttributeMaxDynamicSharedMemorySize,
                             IND3_SMEM_FLOATS * 4);
        smem_set = 1;
    }

    k_gnn<<<NBLK, 256, GNN_SMEM_FLOATS * 4>>>(nodes1, nodes2, edges1, edges2,
                         senders1, receivers1, senders2, receivers2,
                         W_emb_node, b_emb_node, W_emb_edge, b_emb_edge,
                         W_gn_edge, b_gn_edge, W_gn_node, b_gn_node,
                         ap_W0, ap_b0, ap_W1, ap_b1, ap_W2, ap_b2,
                         pp_W0, pp_b0, pp_W1, pp_b1, pp_W2, pp_b2,
                         mp, coords1, coords2);
    k_induct<<<2 * BB, 1024, IND3_SMEM_FLOATS * 4>>>(dist, out);
}